// round 10
// baseline (speedup 1.0000x reference)
#include <cuda_runtime.h>
#include <cstdint>
#include <math.h>

#define HDIM 128
#define MAXN 200000

// ---------------- device scratch ----------------
__device__ float g_mh1[MAXN * HDIM];
__device__ float g_mc1[MAXN * HDIM];
__device__ float g_mh2[MAXN * HDIM];
__device__ float g_mc2[MAXN * HDIM];
__device__ int   g_seg[MAXN + 1];
// transposed + tf32-rounded weights: [phase][n=512][k=256]
__device__ uint32_t g_Bt[2 * 512 * 256];

__device__ __forceinline__ uint32_t smem_u32(const void* p) {
    uint32_t a;
    asm("{ .reg .u64 t; cvta.to.shared.u64 t, %1; cvt.u32.u64 %0, t; }" : "=r"(a) : "l"(p));
    return a;
}
__device__ __forceinline__ uint32_t f2tf32(float f) {
    uint32_t o;
    asm("cvt.rna.tf32.f32 %0, %1;" : "=r"(o) : "f"(f));
    return o;
}
__device__ __forceinline__ void cp_async16(uint32_t dst, const void* src, int src_bytes) {
    asm volatile("cp.async.cg.shared.global [%0], [%1], 16, %2;"
                 :: "r"(dst), "l"(src), "r"(src_bytes) : "memory");
}
__device__ __forceinline__ void cp_commit() {
    asm volatile("cp.async.commit_group;" ::: "memory");
}
__device__ __forceinline__ void cp_wait1() {
    asm volatile("cp.async.wait_group 1;" ::: "memory");
}
__device__ __forceinline__ void cp_wait0() {
    asm volatile("cp.async.wait_group 0;" ::: "memory");
}
__device__ __forceinline__ void mma_tf32(float* d, uint32_t a0, uint32_t a1, uint32_t a2,
                                         uint32_t a3, uint32_t b0, uint32_t b1) {
    asm volatile(
        "mma.sync.aligned.m16n8k8.row.col.f32.tf32.tf32.f32 "
        "{%0,%1,%2,%3}, {%4,%5,%6,%7}, {%8,%9}, {%0,%1,%2,%3};"
        : "+f"(d[0]), "+f"(d[1]), "+f"(d[2]), "+f"(d[3])
        : "r"(a0), "r"(a1), "r"(a2), "r"(a3), "r"(b0), "r"(b1));
}
__device__ __forceinline__ void ldsm_x4(uint32_t& r0, uint32_t& r1, uint32_t& r2, uint32_t& r3,
                                        uint32_t addr) {
    asm volatile("ldmatrix.sync.aligned.m8n8.x4.shared.b16 {%0,%1,%2,%3}, [%4];"
                 : "=r"(r0), "=r"(r1), "=r"(r2), "=r"(r3) : "r"(addr));
}

// ---------------- seg: boundaries of sorted dst -> g_seg[0..n] ----------------
__global__ void seg_kernel(const int* __restrict__ dst, int n, int e)
{
    int i = blockIdx.x * blockDim.x + threadIdx.x;
    if (i > e) return;
    int lo = (i == 0) ? 0 : dst[i - 1] + 1;
    int hi = (i == e) ? n : dst[i];
    for (int v = lo; v <= hi; ++v) g_seg[v] = i;
}

// ---------------- gather: segment sum via precomputed boundaries ----------------
__global__ void gather_kernel(const float* __restrict__ h1, const float* __restrict__ c1,
                              const float* __restrict__ h2, const float* __restrict__ c2,
                              const int* __restrict__ src, int n)
{
    int node = (blockIdx.x * blockDim.x + threadIdx.x) >> 5;
    int lane = threadIdx.x & 31;
    if (node >= n) return;

    int s    = g_seg[node];
    int send = g_seg[node + 1];

    float4 a1 = make_float4(0.f, 0.f, 0.f, 0.f);
    float4 a2 = a1, a3 = a1, a4 = a1;
    const int col = lane * 4;

    int idx = s;
    for (; idx + 4 <= send; idx += 4) {
        int b0 = src[idx + 0] * HDIM + col;
        int b1 = src[idx + 1] * HDIM + col;
        int b2 = src[idx + 2] * HDIM + col;
        int b3 = src[idx + 3] * HDIM + col;
        float4 h1a = *(const float4*)(h1 + b0), h1b = *(const float4*)(h1 + b1);
        float4 h1c = *(const float4*)(h1 + b2), h1d = *(const float4*)(h1 + b3);
        float4 c1a = *(const float4*)(c1 + b0), c1b = *(const float4*)(c1 + b1);
        float4 c1c = *(const float4*)(c1 + b2), c1d = *(const float4*)(c1 + b3);
        float4 h2a = *(const float4*)(h2 + b0), h2b = *(const float4*)(h2 + b1);
        float4 h2c = *(const float4*)(h2 + b2), h2d = *(const float4*)(h2 + b3);
        float4 c2a = *(const float4*)(c2 + b0), c2b = *(const float4*)(c2 + b1);
        float4 c2c = *(const float4*)(c2 + b2), c2d = *(const float4*)(c2 + b3);
        a1.x += (h1a.x + h1b.x) + (h1c.x + h1d.x);
        a1.y += (h1a.y + h1b.y) + (h1c.y + h1d.y);
        a1.z += (h1a.z + h1b.z) + (h1c.z + h1d.z);
        a1.w += (h1a.w + h1b.w) + (h1c.w + h1d.w);
        a2.x += (c1a.x + c1b.x) + (c1c.x + c1d.x);
        a2.y += (c1a.y + c1b.y) + (c1c.y + c1d.y);
        a2.z += (c1a.z + c1b.z) + (c1c.z + c1d.z);
        a2.w += (c1a.w + c1b.w) + (c1c.w + c1d.w);
        a3.x += (h2a.x + h2b.x) + (h2c.x + h2d.x);
        a3.y += (h2a.y + h2b.y) + (h2c.y + h2d.y);
        a3.z += (h2a.z + h2b.z) + (h2c.z + h2d.z);
        a3.w += (h2a.w + h2b.w) + (h2c.w + h2d.w);
        a4.x += (c2a.x + c2b.x) + (c2c.x + c2d.x);
        a4.y += (c2a.y + c2b.y) + (c2c.y + c2d.y);
        a4.z += (c2a.z + c2b.z) + (c2c.z + c2d.z);
        a4.w += (c2a.w + c2b.w) + (c2c.w + c2d.w);
    }
    for (; idx < send; ++idx) {
        int b = src[idx] * HDIM + col;
        float4 v;
        v = *(const float4*)(h1 + b); a1.x += v.x; a1.y += v.y; a1.z += v.z; a1.w += v.w;
        v = *(const float4*)(c1 + b); a2.x += v.x; a2.y += v.y; a2.z += v.z; a2.w += v.w;
        v = *(const float4*)(h2 + b); a3.x += v.x; a3.y += v.y; a3.z += v.z; a3.w += v.w;
        v = *(const float4*)(c2 + b); a4.x += v.x; a4.y += v.y; a4.z += v.z; a4.w += v.w;
    }

    int ob = node * HDIM + col;
    *(float4*)(g_mh1 + ob) = a1;
    *(float4*)(g_mc1 + ob) = a2;
    *(float4*)(g_mh2 + ob) = a3;
    *(float4*)(g_mc2 + ob) = a4;
}

// ---------------- prep: weights -> [n=512][k=256] (B^T), tf32-rounded ----------------
__global__ void prep_kernel(const float* __restrict__ W1, const float* __restrict__ U1,
                            const float* __restrict__ W2, const float* __restrict__ U2)
{
    int p = blockIdx.y;
    int i = blockIdx.x * 256 + threadIdx.x;
    int k = i >> 9, n = i & 511;
    const float* W = p ? W2 : W1;
    const float* U = p ? U2 : U1;
    float v = (k < 128) ? W[k * 512 + n] : U[(k - 128) * 512 + n];
    g_Bt[p * 131072 + n * 256 + k] = f2tf32(v);
}

// ---------------- fused HMMA(tf32) GEMM + gates ----------------
// Tile 128 rows x 64 cols (c = g*16 + hh, h = h0 + hh, h0 = bx*16), K=256, BK=32.
// 8 warps: wm = warp&1 (64-row half), wn = warp>>1 (16-col block).
// acc 32 regs/thread -> 3 CTAs/SM (85-reg cap), 24 warps/SM.
#define S_A0 0
#define S_B0 16384
#define S_A1 24576
#define S_B1 40960
#define ES_STRIDE 68
#define SMEM_TOTAL 49152

__global__ __launch_bounds__(256, 3)
void lstm_mma_kernel(const float* __restrict__ A1,
                     const float* __restrict__ bW, const float* __restrict__ bU,
                     float* __restrict__ h_out, float* __restrict__ c_out,
                     int nrows, int phase)
{
    extern __shared__ char smem[];
    const uint32_t sbase = smem_u32(smem);
    const int tid = threadIdx.x;
    const int h0   = blockIdx.x * 16;
    const int row0 = blockIdx.y * 128;

    const float* A2 = phase ? g_mh2 : g_mh1;
    const float* mc = phase ? g_mc2 : g_mc1;
    const uint32_t* Bt = g_Bt + phase * 131072;

    // ---- lean staging state ----
    const int r0 = tid >> 3;               // 0..31
    const int q  = tid & 7;
    const uint32_t sw0 = (uint32_t)(r0 * 32 + ((q ^ (r0 & 7)) << 2)) * 4;
    const int gr0 = row0 + r0;
    const int grc0 = gr0 * HDIM + q * 4;   // A base element offset (row gr0)
    // B: tile col c = r0 + 32*i -> n = ((r0>>4) + 2*i)*128 + h0 + (r0&15)
    // => per-i offset is a CONSTANT +256 rows = +65536 elements.
    const uint32_t* pB0 = Bt + (size_t)(((r0 >> 4) * 128) + h0 + (r0 & 15)) * 256 + q * 4;

    auto stage = [&](int j, int b) {
        const float* Ap = (j < 4) ? A1 : A2;
        const int koff = (j & 3) * 32;
        const int k0 = j * 32;
        const uint32_t abase = sbase + (b ? S_A1 : S_A0) + sw0;
        const uint32_t bbase = sbase + (b ? S_B1 : S_B0) + sw0;
#pragma unroll
        for (int i = 0; i < 4; ++i) {
            int ok = (gr0 + 32 * i < nrows) ? 16 : 0;
            cp_async16(abase + 4096u * i, Ap + grc0 + 4096 * i + koff, ok);
        }
#pragma unroll
        for (int i = 0; i < 2; ++i)
            cp_async16(bbase + 4096u * i, pB0 + 65536 * i + k0, 16);
        cp_commit();
    };

    const int lane = tid & 31;
    const int warp = tid >> 5;
    const int wm = warp & 1;          // 64-row half
    const int wn = warp >> 1;         // 16-col block (0..3)
    const int g8  = lane >> 2;
    const int tig = lane & 3;
    const int lane7 = lane & 7;

    const uint32_t a_row_off = (uint32_t)(wm * 64 + (lane & 15)) * 128;
    const int a_qsel = lane >> 4;
    const uint32_t b_row_off = (uint32_t)(wn * 16 + lane7 + ((lane >> 4) << 3)) * 128;
    const int b_qsel = (lane >> 3) & 1;

    float acc[4][2][4];
#pragma unroll
    for (int a = 0; a < 4; ++a)
#pragma unroll
        for (int b = 0; b < 2; ++b)
#pragma unroll
            for (int c = 0; c < 4; ++c) acc[a][b][c] = 0.f;

    stage(0, 0);

    for (int j = 0; j < 8; ++j) {
        const int buf = j & 1;
        if (j < 7) { stage(j + 1, buf ^ 1); cp_wait1(); }
        else       { cp_wait0(); }
        __syncthreads();

        const uint32_t Abase = sbase + (buf ? S_A1 : S_A0);
        const uint32_t Bbase = sbase + (buf ? S_B1 : S_B0);

#pragma unroll
        for (int ks = 0; ks < 4; ++ks) {
            uint32_t af[4][4], bf[2][2];
            const uint32_t axor = (uint32_t)(((2 * ks + a_qsel) ^ lane7) << 4);
            const uint32_t bxor = (uint32_t)(((2 * ks + b_qsel) ^ lane7) << 4);
#pragma unroll
            for (int mt = 0; mt < 4; ++mt)
                ldsm_x4(af[mt][0], af[mt][1], af[mt][2], af[mt][3],
                        Abase + a_row_off + (uint32_t)mt * 2048 + axor);
            ldsm_x4(bf[0][0], bf[0][1], bf[1][0], bf[1][1], Bbase + b_row_off + bxor);
#pragma unroll
            for (int mt = 0; mt < 4; ++mt)
#pragma unroll
                for (int nt = 0; nt < 2; ++nt)
                    mma_tf32(acc[mt][nt], af[mt][0], af[mt][1], af[mt][2], af[mt][3],
                             bf[nt][0], bf[nt][1]);
        }
        __syncthreads();
    }

    // ---- park accumulators in smem (Es[128][68]) ----
    float* Es = (float*)smem;
#pragma unroll
    for (int mt = 0; mt < 4; ++mt) {
#pragma unroll
        for (int nt = 0; nt < 2; ++nt) {
            int r = wm * 64 + mt * 16 + g8;
            int c = wn * 16 + nt * 8 + 2 * tig;
            *(float2*)(Es + r * ES_STRIDE + c)       = make_float2(acc[mt][nt][0], acc[mt][nt][1]);
            *(float2*)(Es + (r + 8) * ES_STRIDE + c) = make_float2(acc[mt][nt][2], acc[mt][nt][3]);
        }
    }
    __syncthreads();

    // ---- gate pass: hh = tid&15, rows (tid>>4) + 16*it ----
    {
        const int hh = tid & 15;
        const int rbase = tid >> 4;
        const int h = h0 + hh;
        const float bi = bW[h]       + bU[h];
        const float bo = bW[128 + h] + bU[128 + h];
        const float bu = bW[256 + h] + bU[256 + h];
        const float bfm = bW[384 + h] + bU[384 + h];
#pragma unroll 4
        for (int it = 0; it < 8; ++it) {
            int r = rbase + it * 16;
            int grow = row0 + r;
            if (grow >= nrows) continue;
            // tile col layout: c = g*16 + hh
            float xi = Es[r * ES_STRIDE + hh]      + bi;
            float xo = Es[r * ES_STRIDE + 16 + hh] + bo;
            float xu = Es[r * ES_STRIDE + 32 + hh] + bu;
            float xf = Es[r * ES_STRIDE + 48 + hh] + bfm;
            float gi = 1.f / (1.f + __expf(-xi));
            float go = 1.f / (1.f + __expf(-xo));
            float gu = tanhf(xu);
            float gf = 1.f / (1.f + __expf(-xf));
            float mcv = mc[(size_t)grow * HDIM + h];
            float cn = gi * gu + gf * mcv;
            float hn = go * tanhf(cn);
            c_out[(size_t)grow * HDIM + h] = cn;
            h_out[(size_t)grow * HDIM + h] = hn;
        }
    }
}

// ---------------- host ----------------
extern "C" void kernel_launch(void* const* d_in, const int* in_sizes, int n_in,
                              void* d_out, int out_size)
{
    const float* x   = (const float*)d_in[0];
    const float* h1  = (const float*)d_in[1];
    const float* c1  = (const float*)d_in[2];
    const float* h2  = (const float*)d_in[3];
    const float* c2  = (const float*)d_in[4];
    const float* W1  = (const float*)d_in[5];
    const float* bW1 = (const float*)d_in[6];
    const float* U1  = (const float*)d_in[7];
    const float* bU1 = (const float*)d_in[8];
    const float* W2  = (const float*)d_in[9];
    const float* bW2 = (const float*)d_in[10];
    const float* U2  = (const float*)d_in[11];
    const float* bU2 = (const float*)d_in[12];
    const int*   src = (const int*)d_in[13];
    const int*   dst = (const int*)d_in[14];

    int n = in_sizes[1] / HDIM;
    int e = in_sizes[13];

    float* out = (float*)d_out;
    float* h1n = out;
    float* c1n = out + (size_t)n * HDIM;
    float* h2n = out + 2 * (size_t)n * HDIM;
    float* c2n = out + 3 * (size_t)n * HDIM;

    static int smem_set = 0;
    if (!smem_set) {
        cudaFuncSetAttribute(lstm_mma_kernel,
                             cudaFuncAttributeMaxDynamicSharedMemorySize, SMEM_TOTAL);
        smem_set = 1;
    }

    {
        dim3 grid(512, 2);
        prep_kernel<<<grid, 256>>>(W1, U1, W2, U2);
    }
    seg_kernel<<<(e + 256) / 256, 256>>>(dst, n, e);
    {
        int blocks = (n + 7) / 8;
        gather_kernel<<<blocks, 256>>>(h1, c1, h2, c2, src, n);
    }
    int mtiles = (n + 127) / 128;
    dim3 grid(8, mtiles);
    lstm_mma_kernel<<<grid, 256, SMEM_TOTAL>>>(x, bW1, bU1, h1n, c1n, n, 0);
    lstm_mma_kernel<<<grid, 256, SMEM_TOTAL>>>(c1n, bW2, bU2, h2n, c2n, n, 1);
}

// round 11
// speedup vs baseline: 1.2345x; 1.2345x over previous
#include <cuda_runtime.h>
#include <cstdint>
#include <math.h>

#define HDIM 128
#define MAXN 200000

// ---------------- device scratch ----------------
__device__ float g_mh1[MAXN * HDIM];
__device__ float g_mc1[MAXN * HDIM];
__device__ float g_mh2[MAXN * HDIM];
__device__ float g_mc2[MAXN * HDIM];
__device__ int   g_seg[MAXN + 1];
// transposed + tf32-rounded weights: [phase][n=512][k=256]
__device__ uint32_t g_Bt[2 * 512 * 256];

__device__ __forceinline__ uint32_t smem_u32(const void* p) {
    uint32_t a;
    asm("{ .reg .u64 t; cvta.to.shared.u64 t, %1; cvt.u32.u64 %0, t; }" : "=r"(a) : "l"(p));
    return a;
}
__device__ __forceinline__ uint32_t f2tf32(float f) {
    uint32_t o;
    asm("cvt.rna.tf32.f32 %0, %1;" : "=r"(o) : "f"(f));
    return o;
}
__device__ __forceinline__ void cp_async16(uint32_t dst, const void* src, int src_bytes) {
    asm volatile("cp.async.cg.shared.global [%0], [%1], 16, %2;"
                 :: "r"(dst), "l"(src), "r"(src_bytes) : "memory");
}
__device__ __forceinline__ void cp_commit() {
    asm volatile("cp.async.commit_group;" ::: "memory");
}
__device__ __forceinline__ void cp_wait1() {
    asm volatile("cp.async.wait_group 1;" ::: "memory");
}
__device__ __forceinline__ void cp_wait0() {
    asm volatile("cp.async.wait_group 0;" ::: "memory");
}
__device__ __forceinline__ void mma_tf32(float* d, uint32_t a0, uint32_t a1, uint32_t a2,
                                         uint32_t a3, uint32_t b0, uint32_t b1) {
    asm volatile(
        "mma.sync.aligned.m16n8k8.row.col.f32.tf32.tf32.f32 "
        "{%0,%1,%2,%3}, {%4,%5,%6,%7}, {%8,%9}, {%0,%1,%2,%3};"
        : "+f"(d[0]), "+f"(d[1]), "+f"(d[2]), "+f"(d[3])
        : "r"(a0), "r"(a1), "r"(a2), "r"(a3), "r"(b0), "r"(b1));
}
__device__ __forceinline__ void ldsm_x4(uint32_t& r0, uint32_t& r1, uint32_t& r2, uint32_t& r3,
                                        uint32_t addr) {
    asm volatile("ldmatrix.sync.aligned.m8n8.x4.shared.b16 {%0,%1,%2,%3}, [%4];"
                 : "=r"(r0), "=r"(r1), "=r"(r2), "=r"(r3) : "r"(addr));
}

// ---------------- seg: boundaries of sorted dst -> g_seg[0..n] ----------------
__global__ void seg_kernel(const int* __restrict__ dst, int n, int e)
{
    int i = blockIdx.x * blockDim.x + threadIdx.x;
    if (i > e) return;
    int lo = (i == 0) ? 0 : dst[i - 1] + 1;
    int hi = (i == e) ? n : dst[i];
    for (int v = lo; v <= hi; ++v) g_seg[v] = i;
}

// ---------------- gather: segment sum via precomputed boundaries ----------------
__global__ void gather_kernel(const float* __restrict__ h1, const float* __restrict__ c1,
                              const float* __restrict__ h2, const float* __restrict__ c2,
                              const int* __restrict__ src, int n)
{
    int node = (blockIdx.x * blockDim.x + threadIdx.x) >> 5;
    int lane = threadIdx.x & 31;
    if (node >= n) return;

    int s    = g_seg[node];
    int send = g_seg[node + 1];

    float4 a1 = make_float4(0.f, 0.f, 0.f, 0.f);
    float4 a2 = a1, a3 = a1, a4 = a1;
    const int col = lane * 4;

    int idx = s;
    for (; idx + 4 <= send; idx += 4) {
        int b0 = src[idx + 0] * HDIM + col;
        int b1 = src[idx + 1] * HDIM + col;
        int b2 = src[idx + 2] * HDIM + col;
        int b3 = src[idx + 3] * HDIM + col;
        float4 h1a = *(const float4*)(h1 + b0), h1b = *(const float4*)(h1 + b1);
        float4 h1c = *(const float4*)(h1 + b2), h1d = *(const float4*)(h1 + b3);
        float4 c1a = *(const float4*)(c1 + b0), c1b = *(const float4*)(c1 + b1);
        float4 c1c = *(const float4*)(c1 + b2), c1d = *(const float4*)(c1 + b3);
        float4 h2a = *(const float4*)(h2 + b0), h2b = *(const float4*)(h2 + b1);
        float4 h2c = *(const float4*)(h2 + b2), h2d = *(const float4*)(h2 + b3);
        float4 c2a = *(const float4*)(c2 + b0), c2b = *(const float4*)(c2 + b1);
        float4 c2c = *(const float4*)(c2 + b2), c2d = *(const float4*)(c2 + b3);
        a1.x += (h1a.x + h1b.x) + (h1c.x + h1d.x);
        a1.y += (h1a.y + h1b.y) + (h1c.y + h1d.y);
        a1.z += (h1a.z + h1b.z) + (h1c.z + h1d.z);
        a1.w += (h1a.w + h1b.w) + (h1c.w + h1d.w);
        a2.x += (c1a.x + c1b.x) + (c1c.x + c1d.x);
        a2.y += (c1a.y + c1b.y) + (c1c.y + c1d.y);
        a2.z += (c1a.z + c1b.z) + (c1c.z + c1d.z);
        a2.w += (c1a.w + c1b.w) + (c1c.w + c1d.w);
        a3.x += (h2a.x + h2b.x) + (h2c.x + h2d.x);
        a3.y += (h2a.y + h2b.y) + (h2c.y + h2d.y);
        a3.z += (h2a.z + h2b.z) + (h2c.z + h2d.z);
        a3.w += (h2a.w + h2b.w) + (h2c.w + h2d.w);
        a4.x += (c2a.x + c2b.x) + (c2c.x + c2d.x);
        a4.y += (c2a.y + c2b.y) + (c2c.y + c2d.y);
        a4.z += (c2a.z + c2b.z) + (c2c.z + c2d.z);
        a4.w += (c2a.w + c2b.w) + (c2c.w + c2d.w);
    }
    for (; idx < send; ++idx) {
        int b = src[idx] * HDIM + col;
        float4 v;
        v = *(const float4*)(h1 + b); a1.x += v.x; a1.y += v.y; a1.z += v.z; a1.w += v.w;
        v = *(const float4*)(c1 + b); a2.x += v.x; a2.y += v.y; a2.z += v.z; a2.w += v.w;
        v = *(const float4*)(h2 + b); a3.x += v.x; a3.y += v.y; a3.z += v.z; a3.w += v.w;
        v = *(const float4*)(c2 + b); a4.x += v.x; a4.y += v.y; a4.z += v.z; a4.w += v.w;
    }

    int ob = node * HDIM + col;
    *(float4*)(g_mh1 + ob) = a1;
    *(float4*)(g_mc1 + ob) = a2;
    *(float4*)(g_mh2 + ob) = a3;
    *(float4*)(g_mc2 + ob) = a4;
}

// ---------------- prep: weights -> [n=512][k=256] (B^T), tf32-rounded ----------------
__global__ void prep_kernel(const float* __restrict__ W1, const float* __restrict__ U1,
                            const float* __restrict__ W2, const float* __restrict__ U2)
{
    int p = blockIdx.y;
    int i = blockIdx.x * 256 + threadIdx.x;
    int k = i >> 9, n = i & 511;
    const float* W = p ? W2 : W1;
    const float* U = p ? U2 : U1;
    float v = (k < 128) ? W[k * 512 + n] : U[(k - 128) * 512 + n];
    g_Bt[p * 131072 + n * 256 + k] = f2tf32(v);
}

// ---------------- fused HMMA(tf32) GEMM + gates ----------------
// 128x128 tile, K=256, BK=32, 2-stage, ldmatrix fragments, ks-pipelined frags.
#define S_A0 0
#define S_A1 16384
#define S_B0 32768
#define S_B1 49152
#define ES_STRIDE 132
#define SMEM_TOTAL (128 * ES_STRIDE * 4)   // 67584

__global__ __launch_bounds__(256, 2)
void lstm_mma_kernel(const float* __restrict__ A1,
                     const float* __restrict__ bW, const float* __restrict__ bU,
                     float* __restrict__ h_out, float* __restrict__ c_out,
                     int nrows, int phase)
{
    extern __shared__ char smem[];
    const uint32_t sbase = smem_u32(smem);
    const int tid = threadIdx.x;
    const int h0   = blockIdx.x * 32;
    const int row0 = blockIdx.y * 128;

    const float* A2 = phase ? g_mh2 : g_mh1;
    const float* mc = phase ? g_mc2 : g_mc1;
    const uint32_t* Bt = g_Bt + phase * 131072;

    // ---- lean staging state (constant strides; no arrays) ----
    const int r0 = tid >> 3;               // 0..31
    const int q  = tid & 7;
    const uint32_t sw0 = (uint32_t)(r0 * 32 + ((q ^ (r0 & 7)) << 2)) * 4;
    const int gr0 = row0 + r0;
    const long grc0 = (long)gr0 * HDIM + q * 4;
    // B: tile col c = r0 + 32*i -> n = i*128 + h0 + r0 => stride 32768 elements per i
    const uint32_t* pB0 = Bt + (size_t)(h0 + r0) * 256 + q * 4;

    auto stage = [&](int j, int b) {
        const float* Ap = (j < 4) ? A1 : A2;
        const int koff = (j & 3) * 32;
        const int k0 = j * 32;
        const uint32_t abase = sbase + (b ? S_A1 : S_A0) + sw0;
        const uint32_t bbase = sbase + (b ? S_B1 : S_B0) + sw0;
#pragma unroll
        for (int i = 0; i < 4; ++i) {
            int ok = (gr0 + 32 * i < nrows) ? 16 : 0;
            cp_async16(abase + 4096u * i, Ap + grc0 + 4096 * i + koff, ok);
        }
#pragma unroll
        for (int i = 0; i < 4; ++i)
            cp_async16(bbase + 4096u * i, pB0 + 32768 * i + k0, 16);
        cp_commit();
    };

    const int lane = tid & 31;
    const int warp = tid >> 5;
    const int wm = warp & 1;
    const int wn = warp >> 1;
    const int g8  = lane >> 2;
    const int tig = lane & 3;
    const int lane7 = lane & 7;

    const uint32_t a_row_off = (uint32_t)(wm * 64 + (lane & 15)) * 128;
    const int a_qsel = lane >> 4;
    const uint32_t b_row_off = (uint32_t)(wn * 32 + lane7 + ((lane >> 4) << 3)) * 128;
    const int b_qsel = (lane >> 3) & 1;

    float acc[4][4][4];
#pragma unroll
    for (int a = 0; a < 4; ++a)
#pragma unroll
        for (int b = 0; b < 4; ++b)
#pragma unroll
            for (int c = 0; c < 4; ++c) acc[a][b][c] = 0.f;

    stage(0, 0);

    uint32_t af[2][4][4], bf[2][4][2];

    for (int j = 0; j < 8; ++j) {
        const int buf = j & 1;
        if (j < 7) { stage(j + 1, buf ^ 1); cp_wait1(); }
        else       { cp_wait0(); }
        __syncthreads();

        const uint32_t Abase = sbase + (buf ? S_A1 : S_A0);
        const uint32_t Bbase = sbase + (buf ? S_B1 : S_B0);

        // prime fragments for ks=0
        {
            const uint32_t axor = (uint32_t)(((a_qsel) ^ lane7) << 4);
            const uint32_t bxor = (uint32_t)(((b_qsel) ^ lane7) << 4);
#pragma unroll
            for (int mt = 0; mt < 4; ++mt)
                ldsm_x4(af[0][mt][0], af[0][mt][1], af[0][mt][2], af[0][mt][3],
                        Abase + a_row_off + (uint32_t)mt * 2048 + axor);
            ldsm_x4(bf[0][0][0], bf[0][0][1], bf[0][1][0], bf[0][1][1],
                    Bbase + b_row_off + bxor);
            ldsm_x4(bf[0][2][0], bf[0][2][1], bf[0][3][0], bf[0][3][1],
                    Bbase + b_row_off + 2048 + bxor);
        }

#pragma unroll
        for (int ks = 0; ks < 4; ++ks) {
            const int cur = ks & 1;
            if (ks < 3) {
                const int nxt = cur ^ 1;
                const uint32_t axor = (uint32_t)(((2 * (ks + 1) + a_qsel) ^ lane7) << 4);
                const uint32_t bxor = (uint32_t)(((2 * (ks + 1) + b_qsel) ^ lane7) << 4);
#pragma unroll
                for (int mt = 0; mt < 4; ++mt)
                    ldsm_x4(af[nxt][mt][0], af[nxt][mt][1], af[nxt][mt][2], af[nxt][mt][3],
                            Abase + a_row_off + (uint32_t)mt * 2048 + axor);
                ldsm_x4(bf[nxt][0][0], bf[nxt][0][1], bf[nxt][1][0], bf[nxt][1][1],
                        Bbase + b_row_off + bxor);
                ldsm_x4(bf[nxt][2][0], bf[nxt][2][1], bf[nxt][3][0], bf[nxt][3][1],
                        Bbase + b_row_off + 2048 + bxor);
            }
#pragma unroll
            for (int mt = 0; mt < 4; ++mt)
#pragma unroll
                for (int nt = 0; nt < 4; ++nt)
                    mma_tf32(acc[mt][nt], af[cur][mt][0], af[cur][mt][1],
                             af[cur][mt][2], af[cur][mt][3],
                             bf[cur][nt][0], bf[cur][nt][1]);
        }
        __syncthreads();
    }

    // ---- park accumulators in smem (Es[128][132]) ----
    float* Es = (float*)smem;
#pragma unroll
    for (int mt = 0; mt < 4; ++mt) {
#pragma unroll
        for (int nt = 0; nt < 4; ++nt) {
            int r = wm * 64 + mt * 16 + g8;
            int c = wn * 32 + nt * 8 + 2 * tig;
            *(float2*)(Es + r * ES_STRIDE + c)       = make_float2(acc[mt][nt][0], acc[mt][nt][1]);
            *(float2*)(Es + (r + 8) * ES_STRIDE + c) = make_float2(acc[mt][nt][2], acc[mt][nt][3]);
        }
    }
    __syncthreads();

    // ---- gate pass ----
    {
        const int hh = tid & 31;
        const int rbase = tid >> 5;
        const int h = h0 + hh;
        const float bi = bW[h]       + bU[h];
        const float bo = bW[128 + h] + bU[128 + h];
        const float bu = bW[256 + h] + bU[256 + h];
        const float bfm = bW[384 + h] + bU[384 + h];
#pragma unroll 4
        for (int it = 0; it < 16; ++it) {
            int r = rbase + it * 8;
            int grow = row0 + r;
            if (grow >= nrows) continue;
            float xi = Es[r * ES_STRIDE + hh]      + bi;
            float xo = Es[r * ES_STRIDE + 32 + hh] + bo;
            float xu = Es[r * ES_STRIDE + 64 + hh] + bu;
            float xf = Es[r * ES_STRIDE + 96 + hh] + bfm;
            float gi = 1.f / (1.f + __expf(-xi));
            float go = 1.f / (1.f + __expf(-xo));
            float gu = tanhf(xu);
            float gf = 1.f / (1.f + __expf(-xf));
            float mcv = mc[(size_t)grow * HDIM + h];
            float cn = gi * gu + gf * mcv;
            float hn = go * tanhf(cn);
            c_out[(size_t)grow * HDIM + h] = cn;
            h_out[(size_t)grow * HDIM + h] = hn;
        }
    }
}

// ---------------- host ----------------
extern "C" void kernel_launch(void* const* d_in, const int* in_sizes, int n_in,
                              void* d_out, int out_size)
{
    const float* x   = (const float*)d_in[0];
    const float* h1  = (const float*)d_in[1];
    const float* c1  = (const float*)d_in[2];
    const float* h2  = (const float*)d_in[3];
    const float* c2  = (const float*)d_in[4];
    const float* W1  = (const float*)d_in[5];
    const float* bW1 = (const float*)d_in[6];
    const float* U1  = (const float*)d_in[7];
    const float* bU1 = (const float*)d_in[8];
    const float* W2  = (const float*)d_in[9];
    const float* bW2 = (const float*)d_in[10];
    const float* U2  = (const float*)d_in[11];
    const float* bU2 = (const float*)d_in[12];
    const int*   src = (const int*)d_in[13];
    const int*   dst = (const int*)d_in[14];

    int n = in_sizes[1] / HDIM;
    int e = in_sizes[13];

    float* out = (float*)d_out;
    float* h1n = out;
    float* c1n = out + (size_t)n * HDIM;
    float* h2n = out + 2 * (size_t)n * HDIM;
    float* c2n = out + 3 * (size_t)n * HDIM;

    static int smem_set = 0;
    if (!smem_set) {
        cudaFuncSetAttribute(lstm_mma_kernel,
                             cudaFuncAttributeMaxDynamicSharedMemorySize, SMEM_TOTAL);
        smem_set = 1;
    }

    {
        dim3 grid(512, 2);
        prep_kernel<<<grid, 256>>>(W1, U1, W2, U2);
    }
    seg_kernel<<<(e + 256) / 256, 256>>>(dst, n, e);
    {
        int blocks = (n + 7) / 8;
        gather_kernel<<<blocks, 256>>>(h1, c1, h2, c2, src, n);
    }
    int mtiles = (n + 127) / 128;
    dim3 grid(4, mtiles);
    lstm_mma_kernel<<<grid, 256, SMEM_TOTAL>>>(x, bW1, bU1, h1n, c1n, n, 0);
    lstm_mma_kernel<<<grid, 256, SMEM_TOTAL>>>(c1n, bW2, bU2, h2n, c2n, n, 1);
}

// round 12
// speedup vs baseline: 1.4382x; 1.1649x over previous
#include <cuda_runtime.h>
#include <cuda_fp16.h>
#include <cstdint>
#include <math.h>

#define HDIM 128
#define MAXN 200000

// ---------------- device scratch ----------------
__device__ __half g_x16[MAXN * HDIM];     // fp16 copy of x
__device__ __half g_c1n16[MAXN * HDIM];   // fp16 copy of c1n (phase-0 output)
__device__ __half g_mh1[MAXN * HDIM];     // mailbox h sums, fp16 (GEMM operand)
__device__ __half g_mh2[MAXN * HDIM];
__device__ float  g_mc1[MAXN * HDIM];     // mailbox c sums, fp32 (epilogue operand)
__device__ float  g_mc2[MAXN * HDIM];
__device__ int    g_seg[MAXN + 1];
// transposed fp16 weights: [phase][n=512][k=256]
__device__ __half g_Bt16[2 * 512 * 256];

__device__ __forceinline__ uint32_t smem_u32(const void* p) {
    uint32_t a;
    asm("{ .reg .u64 t; cvta.to.shared.u64 t, %1; cvt.u32.u64 %0, t; }" : "=r"(a) : "l"(p));
    return a;
}
__device__ __forceinline__ void cp_async16(uint32_t dst, const void* src, int src_bytes) {
    asm volatile("cp.async.cg.shared.global [%0], [%1], 16, %2;"
                 :: "r"(dst), "l"(src), "r"(src_bytes) : "memory");
}
__device__ __forceinline__ void cp_commit() {
    asm volatile("cp.async.commit_group;" ::: "memory");
}
__device__ __forceinline__ void cp_wait1() {
    asm volatile("cp.async.wait_group 1;" ::: "memory");
}
__device__ __forceinline__ void cp_wait0() {
    asm volatile("cp.async.wait_group 0;" ::: "memory");
}
__device__ __forceinline__ void mma_f16(float* d, uint32_t a0, uint32_t a1, uint32_t a2,
                                        uint32_t a3, uint32_t b0, uint32_t b1) {
    asm volatile(
        "mma.sync.aligned.m16n8k16.row.col.f32.f16.f16.f32 "
        "{%0,%1,%2,%3}, {%4,%5,%6,%7}, {%8,%9}, {%0,%1,%2,%3};"
        : "+f"(d[0]), "+f"(d[1]), "+f"(d[2]), "+f"(d[3])
        : "r"(a0), "r"(a1), "r"(a2), "r"(a3), "r"(b0), "r"(b1));
}
__device__ __forceinline__ void ldsm_x4(uint32_t& r0, uint32_t& r1, uint32_t& r2, uint32_t& r3,
                                        uint32_t addr) {
    asm volatile("ldmatrix.sync.aligned.m8n8.x4.shared.b16 {%0,%1,%2,%3}, [%4];"
                 : "=r"(r0), "=r"(r1), "=r"(r2), "=r"(r3) : "r"(addr));
}

// ---------------- seg: boundaries of sorted dst -> g_seg[0..n] ----------------
__global__ void seg_kernel(const int* __restrict__ dst, int n, int e)
{
    int i = blockIdx.x * blockDim.x + threadIdx.x;
    if (i > e) return;
    int lo = (i == 0) ? 0 : dst[i - 1] + 1;
    int hi = (i == e) ? n : dst[i];
    for (int v = lo; v <= hi; ++v) g_seg[v] = i;
}

// ---------------- x -> fp16 ----------------
__global__ void x16_kernel(const float* __restrict__ x, int total4)
{
    int i = blockIdx.x * blockDim.x + threadIdx.x;
    if (i >= total4) return;
    float4 v = *(const float4*)(x + i * 4);
    __half2 lo = __floats2half2_rn(v.x, v.y);
    __half2 hi = __floats2half2_rn(v.z, v.w);
    uint2 o; o.x = *(uint32_t*)&lo; o.y = *(uint32_t*)&hi;
    *(uint2*)(g_x16 + i * 4) = o;
}

// ---------------- gather: segment sum; mh -> fp16, mc -> fp32 ----------------
__global__ void gather_kernel(const float* __restrict__ h1, const float* __restrict__ c1,
                              const float* __restrict__ h2, const float* __restrict__ c2,
                              const int* __restrict__ src, int n)
{
    int node = (blockIdx.x * blockDim.x + threadIdx.x) >> 5;
    int lane = threadIdx.x & 31;
    if (node >= n) return;

    int s    = g_seg[node];
    int send = g_seg[node + 1];

    float4 a1 = make_float4(0.f, 0.f, 0.f, 0.f);
    float4 a2 = a1, a3 = a1, a4 = a1;
    const int col = lane * 4;

    int idx = s;
    for (; idx + 4 <= send; idx += 4) {
        int b0 = src[idx + 0] * HDIM + col;
        int b1 = src[idx + 1] * HDIM + col;
        int b2 = src[idx + 2] * HDIM + col;
        int b3 = src[idx + 3] * HDIM + col;
        float4 h1a = *(const float4*)(h1 + b0), h1b = *(const float4*)(h1 + b1);
        float4 h1c = *(const float4*)(h1 + b2), h1d = *(const float4*)(h1 + b3);
        float4 c1a = *(const float4*)(c1 + b0), c1b = *(const float4*)(c1 + b1);
        float4 c1c = *(const float4*)(c1 + b2), c1d = *(const float4*)(c1 + b3);
        float4 h2a = *(const float4*)(h2 + b0), h2b = *(const float4*)(h2 + b1);
        float4 h2c = *(const float4*)(h2 + b2), h2d = *(const float4*)(h2 + b3);
        float4 c2a = *(const float4*)(c2 + b0), c2b = *(const float4*)(c2 + b1);
        float4 c2c = *(const float4*)(c2 + b2), c2d = *(const float4*)(c2 + b3);
        a1.x += (h1a.x + h1b.x) + (h1c.x + h1d.x);
        a1.y += (h1a.y + h1b.y) + (h1c.y + h1d.y);
        a1.z += (h1a.z + h1b.z) + (h1c.z + h1d.z);
        a1.w += (h1a.w + h1b.w) + (h1c.w + h1d.w);
        a2.x += (c1a.x + c1b.x) + (c1c.x + c1d.x);
        a2.y += (c1a.y + c1b.y) + (c1c.y + c1d.y);
        a2.z += (c1a.z + c1b.z) + (c1c.z + c1d.z);
        a2.w += (c1a.w + c1b.w) + (c1c.w + c1d.w);
        a3.x += (h2a.x + h2b.x) + (h2c.x + h2d.x);
        a3.y += (h2a.y + h2b.y) + (h2c.y + h2d.y);
        a3.z += (h2a.z + h2b.z) + (h2c.z + h2d.z);
        a3.w += (h2a.w + h2b.w) + (h2c.w + h2d.w);
        a4.x += (c2a.x + c2b.x) + (c2c.x + c2d.x);
        a4.y += (c2a.y + c2b.y) + (c2c.y + c2d.y);
        a4.z += (c2a.z + c2b.z) + (c2c.z + c2d.z);
        a4.w += (c2a.w + c2b.w) + (c2c.w + c2d.w);
    }
    for (; idx < send; ++idx) {
        int b = src[idx] * HDIM + col;
        float4 v;
        v = *(const float4*)(h1 + b); a1.x += v.x; a1.y += v.y; a1.z += v.z; a1.w += v.w;
        v = *(const float4*)(c1 + b); a2.x += v.x; a2.y += v.y; a2.z += v.z; a2.w += v.w;
        v = *(const float4*)(h2 + b); a3.x += v.x; a3.y += v.y; a3.z += v.z; a3.w += v.w;
        v = *(const float4*)(c2 + b); a4.x += v.x; a4.y += v.y; a4.z += v.z; a4.w += v.w;
    }

    int ob = node * HDIM + col;
    {
        __half2 lo = __floats2half2_rn(a1.x, a1.y);
        __half2 hi = __floats2half2_rn(a1.z, a1.w);
        uint2 o; o.x = *(uint32_t*)&lo; o.y = *(uint32_t*)&hi;
        *(uint2*)(g_mh1 + ob) = o;
    }
    {
        __half2 lo = __floats2half2_rn(a3.x, a3.y);
        __half2 hi = __floats2half2_rn(a3.z, a3.w);
        uint2 o; o.x = *(uint32_t*)&lo; o.y = *(uint32_t*)&hi;
        *(uint2*)(g_mh2 + ob) = o;
    }
    *(float4*)(g_mc1 + ob) = a2;
    *(float4*)(g_mc2 + ob) = a4;
}

// ---------------- prep: weights -> [n=512][k=256] (B^T), fp16 ----------------
__global__ void prep_kernel(const float* __restrict__ W1, const float* __restrict__ U1,
                            const float* __restrict__ W2, const float* __restrict__ U2)
{
    int p = blockIdx.y;
    int i = blockIdx.x * 256 + threadIdx.x;
    int k = i >> 9, n = i & 511;
    const float* W = p ? W2 : W1;
    const float* U = p ? U2 : U1;
    float v = (k < 128) ? W[k * 512 + n] : U[(k - 128) * 512 + n];
    g_Bt16[p * 131072 + n * 256 + k] = __float2half_rn(v);
}

// ---------------- fused HMMA(fp16) GEMM + gates ----------------
// 128x128 tile, K=256, BK=64 fp16 (128B rows -> same swizzle), 4 chunks, 2-stage.
#define S_A0 0
#define S_B0 16384
#define S_A1 32768
#define S_B1 49152
#define ES_STRIDE 132
#define SMEM_TOTAL (128 * ES_STRIDE * 4)   // 67584 (epilogue governs)

__global__ __launch_bounds__(256, 2)
void lstm_mma_kernel(const float* __restrict__ bW, const float* __restrict__ bU,
                     float* __restrict__ h_out, float* __restrict__ c_out,
                     int nrows, int phase)
{
    extern __shared__ char smem[];
    const uint32_t sbase = smem_u32(smem);
    const int tid = threadIdx.x;
    const int h0   = blockIdx.x * 32;
    const int row0 = blockIdx.y * 128;

    const __half* Axx = phase ? g_c1n16 : g_x16;
    const __half* Amh = phase ? g_mh2 : g_mh1;
    const float*  mc  = phase ? g_mc2 : g_mc1;
    const __half* Bt  = g_Bt16 + phase * 131072;

    // ---- staging state: rows of 64 fp16 = 128B, 8x16B chunks ----
    const int r0 = tid >> 3;               // 0..31
    const int q  = tid & 7;
    const uint32_t sw0 = (uint32_t)(r0 * 128 + ((q ^ (r0 & 7)) << 4));
    const int gr0 = row0 + r0;
    const long grc0 = (long)gr0 * HDIM + q * 8;          // half elements
    const __half* pB0 = Bt + (size_t)(h0 + r0) * 256 + q * 8;

    auto stage = [&](int j, int b) {
        const __half* Ap = (j < 2) ? Axx : Amh;
        const int koff = (j & 1) * 64;
        const int k0 = j * 64;
        const uint32_t abase = sbase + (b ? S_A1 : S_A0) + sw0;
        const uint32_t bbase = sbase + (b ? S_B1 : S_B0) + sw0;
#pragma unroll
        for (int i = 0; i < 4; ++i) {
            int ok = (gr0 + 32 * i < nrows) ? 16 : 0;
            cp_async16(abase + 4096u * i, Ap + grc0 + 4096 * i + koff, ok);
        }
#pragma unroll
        for (int i = 0; i < 4; ++i)
            cp_async16(bbase + 4096u * i, pB0 + 32768 * i + k0, 16);
        cp_commit();
    };

    const int lane = tid & 31;
    const int warp = tid >> 5;
    const int wm = warp & 1;
    const int wn = warp >> 1;
    const int g8  = lane >> 2;
    const int tig = lane & 3;
    const int lane7 = lane & 7;

    const uint32_t a_row_off = (uint32_t)(wm * 64 + (lane & 15)) * 128;
    const int a_qsel = lane >> 4;
    const uint32_t b_row_off = (uint32_t)(wn * 32 + lane7 + ((lane >> 4) << 3)) * 128;
    const int b_qsel = (lane >> 3) & 1;

    float acc[4][4][4];
#pragma unroll
    for (int a = 0; a < 4; ++a)
#pragma unroll
        for (int b = 0; b < 4; ++b)
#pragma unroll
            for (int c = 0; c < 4; ++c) acc[a][b][c] = 0.f;

    stage(0, 0);

    for (int j = 0; j < 4; ++j) {
        const int buf = j & 1;
        if (j < 3) { stage(j + 1, buf ^ 1); cp_wait1(); }
        else       { cp_wait0(); }
        __syncthreads();

        const uint32_t Abase = sbase + (buf ? S_A1 : S_A0);
        const uint32_t Bbase = sbase + (buf ? S_B1 : S_B0);

#pragma unroll
        for (int ks = 0; ks < 4; ++ks) {
            uint32_t af[4][4], bf[4][2];
            const uint32_t axor = (uint32_t)(((2 * ks + a_qsel) ^ lane7) << 4);
            const uint32_t bxor = (uint32_t)(((2 * ks + b_qsel) ^ lane7) << 4);
#pragma unroll
            for (int mt = 0; mt < 4; ++mt)
                ldsm_x4(af[mt][0], af[mt][1], af[mt][2], af[mt][3],
                        Abase + a_row_off + (uint32_t)mt * 2048 + axor);
            ldsm_x4(bf[0][0], bf[0][1], bf[1][0], bf[1][1], Bbase + b_row_off + bxor);
            ldsm_x4(bf[2][0], bf[2][1], bf[3][0], bf[3][1], Bbase + b_row_off + 2048 + bxor);
#pragma unroll
            for (int mt = 0; mt < 4; ++mt)
#pragma unroll
                for (int nt = 0; nt < 4; ++nt)
                    mma_f16(acc[mt][nt], af[mt][0], af[mt][1], af[mt][2], af[mt][3],
                            bf[nt][0], bf[nt][1]);
        }
        __syncthreads();
    }

    // ---- park accumulators in smem (Es[128][132]) ----
    float* Es = (float*)smem;
#pragma unroll
    for (int mt = 0; mt < 4; ++mt) {
#pragma unroll
        for (int nt = 0; nt < 4; ++nt) {
            int r = wm * 64 + mt * 16 + g8;
            int c = wn * 32 + nt * 8 + 2 * tig;
            *(float2*)(Es + r * ES_STRIDE + c)       = make_float2(acc[mt][nt][0], acc[mt][nt][1]);
            *(float2*)(Es + (r + 8) * ES_STRIDE + c) = make_float2(acc[mt][nt][2], acc[mt][nt][3]);
        }
    }
    __syncthreads();

    // ---- gate pass ----
    {
        const int hh = tid & 31;
        const int rbase = tid >> 5;
        const int h = h0 + hh;
        const float bi = bW[h]       + bU[h];
        const float bo = bW[128 + h] + bU[128 + h];
        const float bu = bW[256 + h] + bU[256 + h];
        const float bfm = bW[384 + h] + bU[384 + h];
#pragma unroll 4
        for (int it = 0; it < 16; ++it) {
            int r = rbase + it * 8;
            int grow = row0 + r;
            if (grow >= nrows) continue;
            float xi = Es[r * ES_STRIDE + hh]      + bi;
            float xo = Es[r * ES_STRIDE + 32 + hh] + bo;
            float xu = Es[r * ES_STRIDE + 64 + hh] + bu;
            float xf = Es[r * ES_STRIDE + 96 + hh] + bfm;
            float gi = 1.f / (1.f + __expf(-xi));
            float go = 1.f / (1.f + __expf(-xo));
            float gu = tanhf(xu);
            float gf = 1.f / (1.f + __expf(-xf));
            float mcv = mc[(size_t)grow * HDIM + h];
            float cn = gi * gu + gf * mcv;
            float hn = go * tanhf(cn);
            c_out[(size_t)grow * HDIM + h] = cn;
            h_out[(size_t)grow * HDIM + h] = hn;
            if (phase == 0) g_c1n16[(size_t)grow * HDIM + h] = __float2half_rn(cn);
        }
    }
}

// ---------------- host ----------------
extern "C" void kernel_launch(void* const* d_in, const int* in_sizes, int n_in,
                              void* d_out, int out_size)
{
    const float* x   = (const float*)d_in[0];
    const float* h1  = (const float*)d_in[1];
    const float* c1  = (const float*)d_in[2];
    const float* h2  = (const float*)d_in[3];
    const float* c2  = (const float*)d_in[4];
    const float* W1  = (const float*)d_in[5];
    const float* bW1 = (const float*)d_in[6];
    const float* U1  = (const float*)d_in[7];
    const float* bU1 = (const float*)d_in[8];
    const float* W2  = (const float*)d_in[9];
    const float* bW2 = (const float*)d_in[10];
    const float* U2  = (const float*)d_in[11];
    const float* bU2 = (const float*)d_in[12];
    const int*   src = (const int*)d_in[13];
    const int*   dst = (const int*)d_in[14];

    int n = in_sizes[1] / HDIM;
    int e = in_sizes[13];

    float* out = (float*)d_out;
    float* h1n = out;
    float* c1n = out + (size_t)n * HDIM;
    float* h2n = out + 2 * (size_t)n * HDIM;
    float* c2n = out + 3 * (size_t)n * HDIM;

    static int smem_set = 0;
    if (!smem_set) {
        cudaFuncSetAttribute(lstm_mma_kernel,
                             cudaFuncAttributeMaxDynamicSharedMemorySize, SMEM_TOTAL);
        smem_set = 1;
    }

    {
        dim3 grid(512, 2);
        prep_kernel<<<grid, 256>>>(W1, U1, W2, U2);
    }
    x16_kernel<<<(n * 32 + 255) / 256, 256>>>(x, n * 32);
    seg_kernel<<<(e + 256) / 256, 256>>>(dst, n, e);
    {
        int blocks = (n + 7) / 8;
        gather_kernel<<<blocks, 256>>>(h1, c1, h2, c2, src, n);
    }
    int mtiles = (n + 127) / 128;
    dim3 grid(4, mtiles);
    lstm_mma_kernel<<<grid, 256, SMEM_TOTAL>>>(bW1, bU1, h1n, c1n, n, 0);
    lstm_mma_kernel<<<grid, 256, SMEM_TOTAL>>>(bW2, bU2, h2n, c2n, n, 1);
}

// round 13
// speedup vs baseline: 1.4819x; 1.0304x over previous
#include <cuda_runtime.h>
#include <cuda_fp16.h>
#include <cstdint>
#include <math.h>

#define HDIM 128
#define MAXN 200000

// ---------------- device scratch ----------------
__device__ __half g_x16[MAXN * HDIM];     // fp16 copy of x
__device__ __half g_c1n16[MAXN * HDIM];   // fp16 copy of c1n (phase-0 output)
__device__ __half g_mh1[MAXN * HDIM];     // mailbox h sums, fp16 (GEMM operand)
__device__ __half g_mh2[MAXN * HDIM];
__device__ float  g_mc1[MAXN * HDIM];     // mailbox c sums, fp32 (epilogue operand)
__device__ float  g_mc2[MAXN * HDIM];
__device__ int    g_seg[MAXN + 1];
// transposed fp16 weights: [phase][n=512][k=256]
__device__ __half g_Bt16[2 * 512 * 256];

__device__ __forceinline__ uint32_t smem_u32(const void* p) {
    uint32_t a;
    asm("{ .reg .u64 t; cvta.to.shared.u64 t, %1; cvt.u32.u64 %0, t; }" : "=r"(a) : "l"(p));
    return a;
}
__device__ __forceinline__ void cp_async16(uint32_t dst, const void* src, int src_bytes) {
    asm volatile("cp.async.cg.shared.global [%0], [%1], 16, %2;"
                 :: "r"(dst), "l"(src), "r"(src_bytes) : "memory");
}
__device__ __forceinline__ void cp_commit() {
    asm volatile("cp.async.commit_group;" ::: "memory");
}
__device__ __forceinline__ void cp_wait1() {
    asm volatile("cp.async.wait_group 1;" ::: "memory");
}
__device__ __forceinline__ void cp_wait0() {
    asm volatile("cp.async.wait_group 0;" ::: "memory");
}
__device__ __forceinline__ void mma_f16(float* d, uint32_t a0, uint32_t a1, uint32_t a2,
                                        uint32_t a3, uint32_t b0, uint32_t b1) {
    asm volatile(
        "mma.sync.aligned.m16n8k16.row.col.f32.f16.f16.f32 "
        "{%0,%1,%2,%3}, {%4,%5,%6,%7}, {%8,%9}, {%0,%1,%2,%3};"
        : "+f"(d[0]), "+f"(d[1]), "+f"(d[2]), "+f"(d[3])
        : "r"(a0), "r"(a1), "r"(a2), "r"(a3), "r"(b0), "r"(b1));
}
__device__ __forceinline__ void ldsm_x4(uint32_t& r0, uint32_t& r1, uint32_t& r2, uint32_t& r3,
                                        uint32_t addr) {
    asm volatile("ldmatrix.sync.aligned.m8n8.x4.shared.b16 {%0,%1,%2,%3}, [%4];"
                 : "=r"(r0), "=r"(r1), "=r"(r2), "=r"(r3) : "r"(addr));
}

// ---------------- seg: boundaries of sorted dst -> g_seg[0..n] ----------------
__global__ void seg_kernel(const int* __restrict__ dst, int n, int e)
{
    int i = blockIdx.x * blockDim.x + threadIdx.x;
    if (i > e) return;
    int lo = (i == 0) ? 0 : dst[i - 1] + 1;
    int hi = (i == e) ? n : dst[i];
    for (int v = lo; v <= hi; ++v) g_seg[v] = i;
}

// ---------------- x -> fp16 ----------------
__global__ void x16_kernel(const float* __restrict__ x, int total4)
{
    int i = blockIdx.x * blockDim.x + threadIdx.x;
    if (i >= total4) return;
    float4 v = *(const float4*)(x + i * 4);
    __half2 lo = __floats2half2_rn(v.x, v.y);
    __half2 hi = __floats2half2_rn(v.z, v.w);
    uint2 o; o.x = *(uint32_t*)&lo; o.y = *(uint32_t*)&hi;
    *(uint2*)(g_x16 + i * 4) = o;
}

// ---------------- gather (one level): segment sum; mh -> fp16, mc -> fp32 ----------------
__global__ void gather_kernel(const float* __restrict__ ha, const float* __restrict__ ca,
                              const int* __restrict__ src, int n, int level)
{
    int node = (blockIdx.x * blockDim.x + threadIdx.x) >> 5;
    int lane = threadIdx.x & 31;
    if (node >= n) return;

    __half* mh = level ? g_mh2 : g_mh1;
    float*  mc = level ? g_mc2 : g_mc1;

    int s    = g_seg[node];
    int send = g_seg[node + 1];

    float4 ah = make_float4(0.f, 0.f, 0.f, 0.f);
    float4 ac = ah;
    const int col = lane * 4;

    int idx = s;
    for (; idx + 4 <= send; idx += 4) {
        int b0 = src[idx + 0] * HDIM + col;
        int b1 = src[idx + 1] * HDIM + col;
        int b2 = src[idx + 2] * HDIM + col;
        int b3 = src[idx + 3] * HDIM + col;
        float4 va = *(const float4*)(ha + b0), vb = *(const float4*)(ha + b1);
        float4 vc = *(const float4*)(ha + b2), vd = *(const float4*)(ha + b3);
        float4 wa = *(const float4*)(ca + b0), wb = *(const float4*)(ca + b1);
        float4 wc = *(const float4*)(ca + b2), wd = *(const float4*)(ca + b3);
        ah.x += (va.x + vb.x) + (vc.x + vd.x);
        ah.y += (va.y + vb.y) + (vc.y + vd.y);
        ah.z += (va.z + vb.z) + (vc.z + vd.z);
        ah.w += (va.w + vb.w) + (vc.w + vd.w);
        ac.x += (wa.x + wb.x) + (wc.x + wd.x);
        ac.y += (wa.y + wb.y) + (wc.y + wd.y);
        ac.z += (wa.z + wb.z) + (wc.z + wd.z);
        ac.w += (wa.w + wb.w) + (wc.w + wd.w);
    }
    for (; idx < send; ++idx) {
        int b = src[idx] * HDIM + col;
        float4 v = *(const float4*)(ha + b);
        float4 w = *(const float4*)(ca + b);
        ah.x += v.x; ah.y += v.y; ah.z += v.z; ah.w += v.w;
        ac.x += w.x; ac.y += w.y; ac.z += w.z; ac.w += w.w;
    }

    int ob = node * HDIM + col;
    {
        __half2 lo = __floats2half2_rn(ah.x, ah.y);
        __half2 hi = __floats2half2_rn(ah.z, ah.w);
        uint2 o; o.x = *(uint32_t*)&lo; o.y = *(uint32_t*)&hi;
        *(uint2*)(mh + ob) = o;
    }
    *(float4*)(mc + ob) = ac;
}

// ---------------- prep: weights -> [n=512][k=256] (B^T), fp16 ----------------
__global__ void prep_kernel(const float* __restrict__ W1, const float* __restrict__ U1,
                            const float* __restrict__ W2, const float* __restrict__ U2)
{
    int p = blockIdx.y;
    int i = blockIdx.x * 256 + threadIdx.x;
    int k = i >> 9, n = i & 511;
    const float* W = p ? W2 : W1;
    const float* U = p ? U2 : U1;
    float v = (k < 128) ? W[k * 512 + n] : U[(k - 128) * 512 + n];
    g_Bt16[p * 131072 + n * 256 + k] = __float2half_rn(v);
}

// ---------------- fused HMMA(fp16) GEMM + gates ----------------
// 128x128 tile, K=256, BK=64 fp16 (128B rows -> same swizzle), 4 chunks, 2-stage.
#define S_A0 0
#define S_B0 16384
#define S_A1 32768
#define S_B1 49152
#define ES_STRIDE 132
#define SMEM_TOTAL (128 * ES_STRIDE * 4)   // 67584 (epilogue governs)

__global__ __launch_bounds__(256, 2)
void lstm_mma_kernel(const float* __restrict__ bW, const float* __restrict__ bU,
                     float* __restrict__ h_out, float* __restrict__ c_out,
                     int nrows, int phase)
{
    extern __shared__ char smem[];
    const uint32_t sbase = smem_u32(smem);
    const int tid = threadIdx.x;
    const int h0   = blockIdx.x * 32;
    const int row0 = blockIdx.y * 128;

    const __half* Axx = phase ? g_c1n16 : g_x16;
    const __half* Amh = phase ? g_mh2 : g_mh1;
    const float*  mc  = phase ? g_mc2 : g_mc1;
    const __half* Bt  = g_Bt16 + phase * 131072;

    // ---- staging state: rows of 64 fp16 = 128B, 8x16B chunks ----
    const int r0 = tid >> 3;               // 0..31
    const int q  = tid & 7;
    const uint32_t sw0 = (uint32_t)(r0 * 128 + ((q ^ (r0 & 7)) << 4));
    const int gr0 = row0 + r0;
    const long grc0 = (long)gr0 * HDIM + q * 8;          // half elements
    const __half* pB0 = Bt + (size_t)(h0 + r0) * 256 + q * 8;

    auto stage = [&](int j, int b) {
        const __half* Ap = (j < 2) ? Axx : Amh;
        const int koff = (j & 1) * 64;
        const int k0 = j * 64;
        const uint32_t abase = sbase + (b ? S_A1 : S_A0) + sw0;
        const uint32_t bbase = sbase + (b ? S_B1 : S_B0) + sw0;
#pragma unroll
        for (int i = 0; i < 4; ++i) {
            int ok = (gr0 + 32 * i < nrows) ? 16 : 0;
            cp_async16(abase + 4096u * i, Ap + grc0 + 4096 * i + koff, ok);
        }
#pragma unroll
        for (int i = 0; i < 4; ++i)
            cp_async16(bbase + 4096u * i, pB0 + 32768 * i + k0, 16);
        cp_commit();
    };

    const int lane = tid & 31;
    const int warp = tid >> 5;
    const int wm = warp & 1;
    const int wn = warp >> 1;
    const int g8  = lane >> 2;
    const int tig = lane & 3;
    const int lane7 = lane & 7;

    const uint32_t a_row_off = (uint32_t)(wm * 64 + (lane & 15)) * 128;
    const int a_qsel = lane >> 4;
    const uint32_t b_row_off = (uint32_t)(wn * 32 + lane7 + ((lane >> 4) << 3)) * 128;
    const int b_qsel = (lane >> 3) & 1;

    float acc[4][4][4];
#pragma unroll
    for (int a = 0; a < 4; ++a)
#pragma unroll
        for (int b = 0; b < 4; ++b)
#pragma unroll
            for (int c = 0; c < 4; ++c) acc[a][b][c] = 0.f;

    stage(0, 0);

    for (int j = 0; j < 4; ++j) {
        const int buf = j & 1;
        if (j < 3) { stage(j + 1, buf ^ 1); cp_wait1(); }
        else       { cp_wait0(); }
        __syncthreads();

        const uint32_t Abase = sbase + (buf ? S_A1 : S_A0);
        const uint32_t Bbase = sbase + (buf ? S_B1 : S_B0);

#pragma unroll
        for (int ks = 0; ks < 4; ++ks) {
            uint32_t af[4][4], bf[4][2];
            const uint32_t axor = (uint32_t)(((2 * ks + a_qsel) ^ lane7) << 4);
            const uint32_t bxor = (uint32_t)(((2 * ks + b_qsel) ^ lane7) << 4);
#pragma unroll
            for (int mt = 0; mt < 4; ++mt)
                ldsm_x4(af[mt][0], af[mt][1], af[mt][2], af[mt][3],
                        Abase + a_row_off + (uint32_t)mt * 2048 + axor);
            ldsm_x4(bf[0][0], bf[0][1], bf[1][0], bf[1][1], Bbase + b_row_off + bxor);
            ldsm_x4(bf[2][0], bf[2][1], bf[3][0], bf[3][1], Bbase + b_row_off + 2048 + bxor);
#pragma unroll
            for (int mt = 0; mt < 4; ++mt)
#pragma unroll
                for (int nt = 0; nt < 4; ++nt)
                    mma_f16(acc[mt][nt], af[mt][0], af[mt][1], af[mt][2], af[mt][3],
                            bf[nt][0], bf[nt][1]);
        }
        __syncthreads();
    }

    // ---- park accumulators in smem (Es[128][132]) ----
    float* Es = (float*)smem;
#pragma unroll
    for (int mt = 0; mt < 4; ++mt) {
#pragma unroll
        for (int nt = 0; nt < 4; ++nt) {
            int r = wm * 64 + mt * 16 + g8;
            int c = wn * 32 + nt * 8 + 2 * tig;
            *(float2*)(Es + r * ES_STRIDE + c)       = make_float2(acc[mt][nt][0], acc[mt][nt][1]);
            *(float2*)(Es + (r + 8) * ES_STRIDE + c) = make_float2(acc[mt][nt][2], acc[mt][nt][3]);
        }
    }
    __syncthreads();

    // ---- gate pass ----
    {
        const int hh = tid & 31;
        const int rbase = tid >> 5;
        const int h = h0 + hh;
        const float bi = bW[h]       + bU[h];
        const float bo = bW[128 + h] + bU[128 + h];
        const float bu = bW[256 + h] + bU[256 + h];
        const float bfm = bW[384 + h] + bU[384 + h];
#pragma unroll 4
        for (int it = 0; it < 16; ++it) {
            int r = rbase + it * 8;
            int grow = row0 + r;
            if (grow >= nrows) continue;
            float xi = Es[r * ES_STRIDE + hh]      + bi;
            float xo = Es[r * ES_STRIDE + 32 + hh] + bo;
            float xu = Es[r * ES_STRIDE + 64 + hh] + bu;
            float xf = Es[r * ES_STRIDE + 96 + hh] + bfm;
            float gi = 1.f / (1.f + __expf(-xi));
            float go = 1.f / (1.f + __expf(-xo));
            float gu = tanhf(xu);
            float gf = 1.f / (1.f + __expf(-xf));
            float mcv = mc[(size_t)grow * HDIM + h];
            float cn = gi * gu + gf * mcv;
            float hn = go * tanhf(cn);
            c_out[(size_t)grow * HDIM + h] = cn;
            h_out[(size_t)grow * HDIM + h] = hn;
            if (phase == 0) g_c1n16[(size_t)grow * HDIM + h] = __float2half_rn(cn);
        }
    }
}

// ---------------- host ----------------
extern "C" void kernel_launch(void* const* d_in, const int* in_sizes, int n_in,
                              void* d_out, int out_size)
{
    const float* x   = (const float*)d_in[0];
    const float* h1  = (const float*)d_in[1];
    const float* c1  = (const float*)d_in[2];
    const float* h2  = (const float*)d_in[3];
    const float* c2  = (const float*)d_in[4];
    const float* W1  = (const float*)d_in[5];
    const float* bW1 = (const float*)d_in[6];
    const float* U1  = (const float*)d_in[7];
    const float* bU1 = (const float*)d_in[8];
    const float* W2  = (const float*)d_in[9];
    const float* bW2 = (const float*)d_in[10];
    const float* U2  = (const float*)d_in[11];
    const float* bU2 = (const float*)d_in[12];
    const int*   src = (const int*)d_in[13];
    const int*   dst = (const int*)d_in[14];

    int n = in_sizes[1] / HDIM;
    int e = in_sizes[13];

    float* out = (float*)d_out;
    float* h1n = out;
    float* c1n = out + (size_t)n * HDIM;
    float* h2n = out + 2 * (size_t)n * HDIM;
    float* c2n = out + 3 * (size_t)n * HDIM;

    static int inited = 0;
    static cudaStream_t s2;
    static cudaEvent_t evFork, evPrep, evG1, evG2;
    if (!inited) {
        cudaFuncSetAttribute(lstm_mma_kernel,
                             cudaFuncAttributeMaxDynamicSharedMemorySize, SMEM_TOTAL);
        cudaStreamCreateWithFlags(&s2, cudaStreamNonBlocking);
        cudaEventCreateWithFlags(&evFork, cudaEventDisableTiming);
        cudaEventCreateWithFlags(&evPrep, cudaEventDisableTiming);
        cudaEventCreateWithFlags(&evG1,   cudaEventDisableTiming);
        cudaEventCreateWithFlags(&evG2,   cudaEventDisableTiming);
        inited = 1;
    }

    int gblocks = (n + 7) / 8;
    int mtiles = (n + 127) / 128;
    dim3 ggrid(4, mtiles);

    // fork s2 off the main stream
    cudaEventRecord(evFork, 0);
    cudaStreamWaitEvent(s2, evFork, 0);

    // main stream: seg -> gather1
    seg_kernel<<<(e + 256) / 256, 256>>>(dst, n, e);
    // s2: weight/x conversions (independent of seg/gather)
    {
        dim3 pgrid(512, 2);
        prep_kernel<<<pgrid, 256, 0, s2>>>(W1, U1, W2, U2);
        x16_kernel<<<(n * 32 + 255) / 256, 256, 0, s2>>>(x, n * 32);
        cudaEventRecord(evPrep, s2);
    }
    gather_kernel<<<gblocks, 256>>>(h1, c1, src, n, 0);
    cudaEventRecord(evG1, 0);

    // s2: gather2 AFTER gather1 so it overlaps GEMM0, not gather1
    cudaStreamWaitEvent(s2, evG1, 0);
    gather_kernel<<<gblocks, 256, 0, s2>>>(h2, c2, src, n, 1);
    cudaEventRecord(evG2, s2);

    // main: GEMM0 (needs prep/x16 + gather1), then GEMM1 (needs gather2 + c1n)
    cudaStreamWaitEvent(0, evPrep, 0);
    lstm_mma_kernel<<<ggrid, 256, SMEM_TOTAL>>>(bW1, bU1, h1n, c1n, n, 0);
    cudaStreamWaitEvent(0, evG2, 0);
    lstm_mma_kernel<<<ggrid, 256, SMEM_TOTAL>>>(bW2, bU2, h2n, c2n, n, 1);
}

// round 14
// speedup vs baseline: 1.6654x; 1.1238x over previous
#include <cuda_runtime.h>
#include <cuda_fp16.h>
#include <cstdint>
#include <math.h>

#define HDIM 128
#define MAXN 200000
#define NCH 4

// ---------------- device scratch ----------------
__device__ __half g_x16[MAXN * HDIM];     // fp16 copy of x
__device__ __half g_c1n16[MAXN * HDIM];   // fp16 copy of c1n (phase-0 output)
__device__ __half g_mh1[MAXN * HDIM];     // mailbox h sums, fp16
__device__ __half g_mh2[MAXN * HDIM];
__device__ __half g_mc1[MAXN * HDIM];     // mailbox c sums, fp16
__device__ __half g_mc2[MAXN * HDIM];
__device__ int    g_seg[MAXN + 1];
// transposed fp16 weights: [phase][n=512][k=256]
__device__ __half g_Bt16[2 * 512 * 256];

__device__ __forceinline__ uint32_t smem_u32(const void* p) {
    uint32_t a;
    asm("{ .reg .u64 t; cvta.to.shared.u64 t, %1; cvt.u32.u64 %0, t; }" : "=r"(a) : "l"(p));
    return a;
}
__device__ __forceinline__ void cp_async16(uint32_t dst, const void* src, int src_bytes) {
    asm volatile("cp.async.cg.shared.global [%0], [%1], 16, %2;"
                 :: "r"(dst), "l"(src), "r"(src_bytes) : "memory");
}
__device__ __forceinline__ void cp_commit() {
    asm volatile("cp.async.commit_group;" ::: "memory");
}
__device__ __forceinline__ void cp_wait1() {
    asm volatile("cp.async.wait_group 1;" ::: "memory");
}
__device__ __forceinline__ void cp_wait0() {
    asm volatile("cp.async.wait_group 0;" ::: "memory");
}
__device__ __forceinline__ void mma_f16(float* d, uint32_t a0, uint32_t a1, uint32_t a2,
                                        uint32_t a3, uint32_t b0, uint32_t b1) {
    asm volatile(
        "mma.sync.aligned.m16n8k16.row.col.f32.f16.f16.f32 "
        "{%0,%1,%2,%3}, {%4,%5,%6,%7}, {%8,%9}, {%0,%1,%2,%3};"
        : "+f"(d[0]), "+f"(d[1]), "+f"(d[2]), "+f"(d[3])
        : "r"(a0), "r"(a1), "r"(a2), "r"(a3), "r"(b0), "r"(b1));
}
__device__ __forceinline__ void ldsm_x4(uint32_t& r0, uint32_t& r1, uint32_t& r2, uint32_t& r3,
                                        uint32_t addr) {
    asm volatile("ldmatrix.sync.aligned.m8n8.x4.shared.b16 {%0,%1,%2,%3}, [%4];"
                 : "=r"(r0), "=r"(r1), "=r"(r2), "=r"(r3) : "r"(addr));
}
__device__ __forceinline__ float sigmoid_f(float x) {
    return __fdividef(1.f, 1.f + __expf(-x));
}
__device__ __forceinline__ float tanh_f(float x) {
    // saturates correctly for large |x| (expf->inf => 2/inf = 0 => 1)
    return 1.f - __fdividef(2.f, __expf(2.f * x) + 1.f);
}

// ---------------- seg: boundaries of sorted dst -> g_seg[0..n] ----------------
__global__ void seg_kernel(const int* __restrict__ dst, int n, int e)
{
    int i = blockIdx.x * blockDim.x + threadIdx.x;
    if (i > e) return;
    int lo = (i == 0) ? 0 : dst[i - 1] + 1;
    int hi = (i == e) ? n : dst[i];
    for (int v = lo; v <= hi; ++v) g_seg[v] = i;
}

// ---------------- x -> fp16 ----------------
__global__ void x16_kernel(const float* __restrict__ x, int total4)
{
    int i = blockIdx.x * blockDim.x + threadIdx.x;
    if (i >= total4) return;
    float4 v = *(const float4*)(x + i * 4);
    __half2 lo = __floats2half2_rn(v.x, v.y);
    __half2 hi = __floats2half2_rn(v.z, v.w);
    uint2 o; o.x = *(uint32_t*)&lo; o.y = *(uint32_t*)&hi;
    *(uint2*)(g_x16 + i * 4) = o;
}

// ---------------- gather (one level, node range [n0,n1)): mh,mc -> fp16 ----------------
__global__ void gather_kernel(const float* __restrict__ ha, const float* __restrict__ ca,
                              const int* __restrict__ src, int n0, int n1, int level)
{
    int node = ((blockIdx.x * blockDim.x + threadIdx.x) >> 5) + n0;
    int lane = threadIdx.x & 31;
    if (node >= n1) return;

    __half* mh = level ? g_mh2 : g_mh1;
    __half* mc = level ? g_mc2 : g_mc1;

    int s    = g_seg[node];
    int send = g_seg[node + 1];

    float4 ah = make_float4(0.f, 0.f, 0.f, 0.f);
    float4 ac = ah;
    const int col = lane * 4;

    int idx = s;
    for (; idx + 4 <= send; idx += 4) {
        int b0 = src[idx + 0] * HDIM + col;
        int b1 = src[idx + 1] * HDIM + col;
        int b2 = src[idx + 2] * HDIM + col;
        int b3 = src[idx + 3] * HDIM + col;
        float4 va = *(const float4*)(ha + b0), vb = *(const float4*)(ha + b1);
        float4 vc = *(const float4*)(ha + b2), vd = *(const float4*)(ha + b3);
        float4 wa = *(const float4*)(ca + b0), wb = *(const float4*)(ca + b1);
        float4 wc = *(const float4*)(ca + b2), wd = *(const float4*)(ca + b3);
        ah.x += (va.x + vb.x) + (vc.x + vd.x);
        ah.y += (va.y + vb.y) + (vc.y + vd.y);
        ah.z += (va.z + vb.z) + (vc.z + vd.z);
        ah.w += (va.w + vb.w) + (vc.w + vd.w);
        ac.x += (wa.x + wb.x) + (wc.x + wd.x);
        ac.y += (wa.y + wb.y) + (wc.y + wd.y);
        ac.z += (wa.z + wb.z) + (wc.z + wd.z);
        ac.w += (wa.w + wb.w) + (wc.w + wd.w);
    }
    for (; idx < send; ++idx) {
        int b = src[idx] * HDIM + col;
        float4 v = *(const float4*)(ha + b);
        float4 w = *(const float4*)(ca + b);
        ah.x += v.x; ah.y += v.y; ah.z += v.z; ah.w += v.w;
        ac.x += w.x; ac.y += w.y; ac.z += w.z; ac.w += w.w;
    }

    int ob = node * HDIM + col;
    {
        __half2 lo = __floats2half2_rn(ah.x, ah.y);
        __half2 hi = __floats2half2_rn(ah.z, ah.w);
        uint2 o; o.x = *(uint32_t*)&lo; o.y = *(uint32_t*)&hi;
        *(uint2*)(mh + ob) = o;
    }
    {
        __half2 lo = __floats2half2_rn(ac.x, ac.y);
        __half2 hi = __floats2half2_rn(ac.z, ac.w);
        uint2 o; o.x = *(uint32_t*)&lo; o.y = *(uint32_t*)&hi;
        *(uint2*)(mc + ob) = o;
    }
}

// ---------------- prep: weights -> [n=512][k=256] (B^T), fp16 ----------------
__global__ void prep_kernel(const float* __restrict__ W1, const float* __restrict__ U1,
                            const float* __restrict__ W2, const float* __restrict__ U2)
{
    int p = blockIdx.y;
    int i = blockIdx.x * 256 + threadIdx.x;
    int k = i >> 9, n = i & 511;
    const float* W = p ? W2 : W1;
    const float* U = p ? U2 : U1;
    float v = (k < 128) ? W[k * 512 + n] : U[(k - 128) * 512 + n];
    g_Bt16[p * 131072 + n * 256 + k] = __float2half_rn(v);
}

// ---------------- fused HMMA(fp16) GEMM + gates ----------------
#define S_A0 0
#define S_B0 16384
#define S_A1 32768
#define S_B1 49152
#define ES_STRIDE 132
#define SMEM_TOTAL (128 * ES_STRIDE * 4)   // 67584

__global__ __launch_bounds__(256, 2)
void lstm_mma_kernel(const float* __restrict__ bW, const float* __restrict__ bU,
                     float* __restrict__ h_out, float* __restrict__ c_out,
                     int nrows, int phase, int tile_base)
{
    extern __shared__ char smem[];
    const uint32_t sbase = smem_u32(smem);
    const int tid = threadIdx.x;
    const int h0   = blockIdx.x * 32;
    const int row0 = (blockIdx.y + tile_base) * 128;

    const __half* Axx = phase ? g_c1n16 : g_x16;
    const __half* Amh = phase ? g_mh2 : g_mh1;
    const __half* mc  = phase ? g_mc2 : g_mc1;
    const __half* Bt  = g_Bt16 + phase * 131072;

    const int r0 = tid >> 3;
    const int q  = tid & 7;
    const uint32_t sw0 = (uint32_t)(r0 * 128 + ((q ^ (r0 & 7)) << 4));
    const int gr0 = row0 + r0;
    const long grc0 = (long)gr0 * HDIM + q * 8;
    const __half* pB0 = Bt + (size_t)(h0 + r0) * 256 + q * 8;

    auto stage = [&](int j, int b) {
        const __half* Ap = (j < 2) ? Axx : Amh;
        const int koff = (j & 1) * 64;
        const int k0 = j * 64;
        const uint32_t abase = sbase + (b ? S_A1 : S_A0) + sw0;
        const uint32_t bbase = sbase + (b ? S_B1 : S_B0) + sw0;
#pragma unroll
        for (int i = 0; i < 4; ++i) {
            int ok = (gr0 + 32 * i < nrows) ? 16 : 0;
            cp_async16(abase + 4096u * i, Ap + grc0 + 4096 * i + koff, ok);
        }
#pragma unroll
        for (int i = 0; i < 4; ++i)
            cp_async16(bbase + 4096u * i, pB0 + 32768 * i + k0, 16);
        cp_commit();
    };

    const int lane = tid & 31;
    const int warp = tid >> 5;
    const int wm = warp & 1;
    const int wn = warp >> 1;
    const int g8  = lane >> 2;
    const int tig = lane & 3;
    const int lane7 = lane & 7;

    const uint32_t a_row_off = (uint32_t)(wm * 64 + (lane & 15)) * 128;
    const int a_qsel = lane >> 4;
    const uint32_t b_row_off = (uint32_t)(wn * 32 + lane7 + ((lane >> 4) << 3)) * 128;
    const int b_qsel = (lane >> 3) & 1;

    float acc[4][4][4];
#pragma unroll
    for (int a = 0; a < 4; ++a)
#pragma unroll
        for (int b = 0; b < 4; ++b)
#pragma unroll
            for (int c = 0; c < 4; ++c) acc[a][b][c] = 0.f;

    stage(0, 0);

    for (int j = 0; j < 4; ++j) {
        const int buf = j & 1;
        if (j < 3) { stage(j + 1, buf ^ 1); cp_wait1(); }
        else       { cp_wait0(); }
        __syncthreads();

        const uint32_t Abase = sbase + (buf ? S_A1 : S_A0);
        const uint32_t Bbase = sbase + (buf ? S_B1 : S_B0);

#pragma unroll
        for (int ks = 0; ks < 4; ++ks) {
            uint32_t af[4][4], bf[4][2];
            const uint32_t axor = (uint32_t)(((2 * ks + a_qsel) ^ lane7) << 4);
            const uint32_t bxor = (uint32_t)(((2 * ks + b_qsel) ^ lane7) << 4);
#pragma unroll
            for (int mt = 0; mt < 4; ++mt)
                ldsm_x4(af[mt][0], af[mt][1], af[mt][2], af[mt][3],
                        Abase + a_row_off + (uint32_t)mt * 2048 + axor);
            ldsm_x4(bf[0][0], bf[0][1], bf[1][0], bf[1][1], Bbase + b_row_off + bxor);
            ldsm_x4(bf[2][0], bf[2][1], bf[3][0], bf[3][1], Bbase + b_row_off + 2048 + bxor);
#pragma unroll
            for (int mt = 0; mt < 4; ++mt)
#pragma unroll
                for (int nt = 0; nt < 4; ++nt)
                    mma_f16(acc[mt][nt], af[mt][0], af[mt][1], af[mt][2], af[mt][3],
                            bf[nt][0], bf[nt][1]);
        }
        __syncthreads();
    }

    // ---- park accumulators in smem (Es[128][132]) ----
    float* Es = (float*)smem;
#pragma unroll
    for (int mt = 0; mt < 4; ++mt) {
#pragma unroll
        for (int nt = 0; nt < 4; ++nt) {
            int r = wm * 64 + mt * 16 + g8;
            int c = wn * 32 + nt * 8 + 2 * tig;
            *(float2*)(Es + r * ES_STRIDE + c)       = make_float2(acc[mt][nt][0], acc[mt][nt][1]);
            *(float2*)(Es + (r + 8) * ES_STRIDE + c) = make_float2(acc[mt][nt][2], acc[mt][nt][3]);
        }
    }
    __syncthreads();

    // ---- gate pass ----
    {
        const int hh = tid & 31;
        const int rbase = tid >> 5;
        const int h = h0 + hh;
        const float bi = bW[h]       + bU[h];
        const float bo = bW[128 + h] + bU[128 + h];
        const float bu = bW[256 + h] + bU[256 + h];
        const float bfm = bW[384 + h] + bU[384 + h];
#pragma unroll 4
        for (int it = 0; it < 16; ++it) {
            int r = rbase + it * 8;
            int grow = row0 + r;
            if (grow >= nrows) continue;
            float xi = Es[r * ES_STRIDE + hh]      + bi;
            float xo = Es[r * ES_STRIDE + 32 + hh] + bo;
            float xu = Es[r * ES_STRIDE + 64 + hh] + bu;
            float xf = Es[r * ES_STRIDE + 96 + hh] + bfm;
            float gi = sigmoid_f(xi);
            float go = sigmoid_f(xo);
            float gu = tanh_f(xu);
            float gf = sigmoid_f(xf);
            float mcv = __half2float(mc[(size_t)grow * HDIM + h]);
            float cn = gi * gu + gf * mcv;
            float hn = go * tanh_f(cn);
            c_out[(size_t)grow * HDIM + h] = cn;
            h_out[(size_t)grow * HDIM + h] = hn;
            if (phase == 0) g_c1n16[(size_t)grow * HDIM + h] = __float2half_rn(cn);
        }
    }
}

// ---------------- host ----------------
extern "C" void kernel_launch(void* const* d_in, const int* in_sizes, int n_in,
                              void* d_out, int out_size)
{
    const float* x   = (const float*)d_in[0];
    const float* h1  = (const float*)d_in[1];
    const float* c1  = (const float*)d_in[2];
    const float* h2  = (const float*)d_in[3];
    const float* c2  = (const float*)d_in[4];
    const float* W1  = (const float*)d_in[5];
    const float* bW1 = (const float*)d_in[6];
    const float* U1  = (const float*)d_in[7];
    const float* bU1 = (const float*)d_in[8];
    const float* W2  = (const float*)d_in[9];
    const float* bW2 = (const float*)d_in[10];
    const float* U2  = (const float*)d_in[11];
    const float* bU2 = (const float*)d_in[12];
    const int*   src = (const int*)d_in[13];
    const int*   dst = (const int*)d_in[14];

    int n = in_sizes[1] / HDIM;
    int e = in_sizes[13];

    float* out = (float*)d_out;
    float* h1n = out;
    float* c1n = out + (size_t)n * HDIM;
    float* h2n = out + 2 * (size_t)n * HDIM;
    float* c2n = out + 3 * (size_t)n * HDIM;

    static int inited = 0;
    static cudaStream_t sG;
    static cudaEvent_t evFork, evG1[NCH], evG2[NCH];
    if (!inited) {
        cudaFuncSetAttribute(lstm_mma_kernel,
                             cudaFuncAttributeMaxDynamicSharedMemorySize, SMEM_TOTAL);
        int plo, phi;
        cudaDeviceGetStreamPriorityRange(&plo, &phi);
        cudaStreamCreateWithPriority(&sG, cudaStreamNonBlocking, phi);  // high priority
        cudaEventCreateWithFlags(&evFork, cudaEventDisableTiming);
        for (int k = 0; k < NCH; ++k) {
            cudaEventCreateWithFlags(&evG1[k], cudaEventDisableTiming);
            cudaEventCreateWithFlags(&evG2[k], cudaEventDisableTiming);
        }
        inited = 1;
    }

    int mtiles = (n + 127) / 128;
    int mt_per = (mtiles + NCH - 1) / NCH;

    // fork gather stream
    cudaEventRecord(evFork, 0);
    cudaStreamWaitEvent(sG, evFork, 0);

    // gather stream: seg -> gather1 chunks -> gather2 chunks
    seg_kernel<<<(e + 256) / 256, 256, 0, sG>>>(dst, n, e);
    for (int k = 0; k < NCH; ++k) {
        int tb = k * mt_per, te = min(mtiles, tb + mt_per);
        if (tb >= te) { cudaEventRecord(evG1[k], sG); continue; }
        int n0 = tb * 128, n1 = min(n, te * 128);
        int cnt = n1 - n0;
        gather_kernel<<<(cnt * 32 + 255) / 256, 256, 0, sG>>>(h1, c1, src, n0, n1, 0);
        cudaEventRecord(evG1[k], sG);
    }
    for (int k = 0; k < NCH; ++k) {
        int tb = k * mt_per, te = min(mtiles, tb + mt_per);
        if (tb >= te) { cudaEventRecord(evG2[k], sG); continue; }
        int n0 = tb * 128, n1 = min(n, te * 128);
        int cnt = n1 - n0;
        gather_kernel<<<(cnt * 32 + 255) / 256, 256, 0, sG>>>(h2, c2, src, n0, n1, 1);
        cudaEventRecord(evG2[k], sG);
    }

    // main stream: conversions, then chunked GEMM0, then chunked GEMM1
    {
        dim3 pgrid(512, 2);
        prep_kernel<<<pgrid, 256>>>(W1, U1, W2, U2);
        x16_kernel<<<(n * 32 + 255) / 256, 256>>>(x, n * 32);
    }
    for (int k = 0; k < NCH; ++k) {
        int tb = k * mt_per, te = min(mtiles, tb + mt_per);
        if (tb >= te) continue;
        cudaStreamWaitEvent(0, evG1[k], 0);
        dim3 grid(4, te - tb);
        lstm_mma_kernel<<<grid, 256, SMEM_TOTAL>>>(bW1, bU1, h1n, c1n, n, 0, tb);
    }
    for (int k = 0; k < NCH; ++k) {
        int tb = k * mt_per, te = min(mtiles, tb + mt_per);
        if (tb >= te) continue;
        cudaStreamWaitEvent(0, evG2[k], 0);
        dim3 grid(4, te - tb);
        lstm_mma_kernel<<<grid, 256, SMEM_TOTAL>>>(bW2, bU2, h2n, c2n, n, 1, tb);
    }
}

// round 15
// speedup vs baseline: 2.0478x; 1.2296x over previous
#include <cuda_runtime.h>
#include <cuda_fp16.h>
#include <cstdint>
#include <math.h>

#define HDIM 128
#define MAXN 200000
#define NCH 4

// ---------------- device scratch ----------------
__device__ __half g_x16[MAXN * HDIM];     // fp16 copy of x
__device__ __half g_c1n16[MAXN * HDIM];   // fp16 copy of c1n (phase-0 output)
__device__ __half g_mh1[MAXN * HDIM];     // mailbox h sums, fp16
__device__ __half g_mh2[MAXN * HDIM];
__device__ __half g_mc1[MAXN * HDIM];     // mailbox c sums, fp16
__device__ __half g_mc2[MAXN * HDIM];
__device__ int    g_seg[MAXN + 1];
// transposed fp16 weights: [phase][n=512][k=256]
__device__ __half g_Bt16[2 * 512 * 256];

__device__ __forceinline__ uint32_t smem_u32(const void* p) {
    uint32_t a;
    asm("{ .reg .u64 t; cvta.to.shared.u64 t, %1; cvt.u32.u64 %0, t; }" : "=r"(a) : "l"(p));
    return a;
}
__device__ __forceinline__ void cp_async16(uint32_t dst, const void* src, int src_bytes) {
    asm volatile("cp.async.cg.shared.global [%0], [%1], 16, %2;"
                 :: "r"(dst), "l"(src), "r"(src_bytes) : "memory");
}
__device__ __forceinline__ void cp_commit() {
    asm volatile("cp.async.commit_group;" ::: "memory");
}
__device__ __forceinline__ void cp_wait1() {
    asm volatile("cp.async.wait_group 1;" ::: "memory");
}
__device__ __forceinline__ void cp_wait0() {
    asm volatile("cp.async.wait_group 0;" ::: "memory");
}
__device__ __forceinline__ void mma_f16(float* d, uint32_t a0, uint32_t a1, uint32_t a2,
                                        uint32_t a3, uint32_t b0, uint32_t b1) {
    asm volatile(
        "mma.sync.aligned.m16n8k16.row.col.f32.f16.f16.f32 "
        "{%0,%1,%2,%3}, {%4,%5,%6,%7}, {%8,%9}, {%0,%1,%2,%3};"
        : "+f"(d[0]), "+f"(d[1]), "+f"(d[2]), "+f"(d[3])
        : "r"(a0), "r"(a1), "r"(a2), "r"(a3), "r"(b0), "r"(b1));
}
__device__ __forceinline__ void ldsm_x4(uint32_t& r0, uint32_t& r1, uint32_t& r2, uint32_t& r3,
                                        uint32_t addr) {
    asm volatile("ldmatrix.sync.aligned.m8n8.x4.shared.b16 {%0,%1,%2,%3}, [%4];"
                 : "=r"(r0), "=r"(r1), "=r"(r2), "=r"(r3) : "r"(addr));
}
__device__ __forceinline__ float sigmoid_f(float x) {
    return __fdividef(1.f, 1.f + __expf(-x));
}
__device__ __forceinline__ float tanh_f(float x) {
    return 1.f - __fdividef(2.f, __expf(2.f * x) + 1.f);
}

// ---------------- seg ----------------
__global__ void seg_kernel(const int* __restrict__ dst, int n, int e)
{
    int i = blockIdx.x * blockDim.x + threadIdx.x;
    if (i > e) return;
    int lo = (i == 0) ? 0 : dst[i - 1] + 1;
    int hi = (i == e) ? n : dst[i];
    for (int v = lo; v <= hi; ++v) g_seg[v] = i;
}

// ---------------- x -> fp16 ----------------
__global__ void x16_kernel(const float* __restrict__ x, int total4)
{
    int i = blockIdx.x * blockDim.x + threadIdx.x;
    if (i >= total4) return;
    float4 v = *(const float4*)(x + i * 4);
    __half2 lo = __floats2half2_rn(v.x, v.y);
    __half2 hi = __floats2half2_rn(v.z, v.w);
    uint2 o; o.x = *(uint32_t*)&lo; o.y = *(uint32_t*)&hi;
    *(uint2*)(g_x16 + i * 4) = o;
}

// ---------------- gather ----------------
__global__ void gather_kernel(const float* __restrict__ ha, const float* __restrict__ ca,
                              const int* __restrict__ src, int n0, int n1, int level)
{
    int node = ((blockIdx.x * blockDim.x + threadIdx.x) >> 5) + n0;
    int lane = threadIdx.x & 31;
    if (node >= n1) return;

    __half* mh = level ? g_mh2 : g_mh1;
    __half* mc = level ? g_mc2 : g_mc1;

    int s    = g_seg[node];
    int send = g_seg[node + 1];

    float4 ah = make_float4(0.f, 0.f, 0.f, 0.f);
    float4 ac = ah;
    const int col = lane * 4;

    int idx = s;
    for (; idx + 4 <= send; idx += 4) {
        int b0 = src[idx + 0] * HDIM + col;
        int b1 = src[idx + 1] * HDIM + col;
        int b2 = src[idx + 2] * HDIM + col;
        int b3 = src[idx + 3] * HDIM + col;
        float4 va = *(const float4*)(ha + b0), vb = *(const float4*)(ha + b1);
        float4 vc = *(const float4*)(ha + b2), vd = *(const float4*)(ha + b3);
        float4 wa = *(const float4*)(ca + b0), wb = *(const float4*)(ca + b1);
        float4 wc = *(const float4*)(ca + b2), wd = *(const float4*)(ca + b3);
        ah.x += (va.x + vb.x) + (vc.x + vd.x);
        ah.y += (va.y + vb.y) + (vc.y + vd.y);
        ah.z += (va.z + vb.z) + (vc.z + vd.z);
        ah.w += (va.w + vb.w) + (vc.w + vd.w);
        ac.x += (wa.x + wb.x) + (wc.x + wd.x);
        ac.y += (wa.y + wb.y) + (wc.y + wd.y);
        ac.z += (wa.z + wb.z) + (wc.z + wd.z);
        ac.w += (wa.w + wb.w) + (wc.w + wd.w);
    }
    for (; idx < send; ++idx) {
        int b = src[idx] * HDIM + col;
        float4 v = *(const float4*)(ha + b);
        float4 w = *(const float4*)(ca + b);
        ah.x += v.x; ah.y += v.y; ah.z += v.z; ah.w += v.w;
        ac.x += w.x; ac.y += w.y; ac.z += w.z; ac.w += w.w;
    }

    int ob = node * HDIM + col;
    {
        __half2 lo = __floats2half2_rn(ah.x, ah.y);
        __half2 hi = __floats2half2_rn(ah.z, ah.w);
        uint2 o; o.x = *(uint32_t*)&lo; o.y = *(uint32_t*)&hi;
        *(uint2*)(mh + ob) = o;
    }
    {
        __half2 lo = __floats2half2_rn(ac.x, ac.y);
        __half2 hi = __floats2half2_rn(ac.z, ac.w);
        uint2 o; o.x = *(uint32_t*)&lo; o.y = *(uint32_t*)&hi;
        *(uint2*)(mc + ob) = o;
    }
}

// ---------------- prep ----------------
__global__ void prep_kernel(const float* __restrict__ W1, const float* __restrict__ U1,
                            const float* __restrict__ W2, const float* __restrict__ U2)
{
    int p = blockIdx.y;
    int i = blockIdx.x * 256 + threadIdx.x;
    int k = i >> 9, n = i & 511;
    const float* W = p ? W2 : W1;
    const float* U = p ? U2 : U1;
    float v = (k < 128) ? W[k * 512 + n] : U[(k - 128) * 512 + n];
    g_Bt16[p * 131072 + n * 256 + k] = __float2half_rn(v);
}

// ---------------- fused HMMA(fp16) GEMM + in-register gates ----------------
// Gate-aware col permutation: smem row r -> weight col g*128 + h0 + hh,
// g=(r>>3)&3, hh=(r>>5)*8+(r&7). Warp wn owns hh octet wn*8..+8; nt == gate.
#define S_A0 0
#define S_B0 16384
#define S_A1 32768
#define S_B1 49152
#define SMEM_TOTAL 65536

__global__ __launch_bounds__(256, 2)
void lstm_mma_kernel(const float* __restrict__ bW, const float* __restrict__ bU,
                     float* __restrict__ h_out, float* __restrict__ c_out,
                     int nrows, int phase, int tile_base)
{
    extern __shared__ char smem[];
    const uint32_t sbase = smem_u32(smem);
    const int tid = threadIdx.x;
    const int h0   = blockIdx.x * 32;
    const int row0 = (blockIdx.y + tile_base) * 128;

    const __half* Axx = phase ? g_c1n16 : g_x16;
    const __half* Amh = phase ? g_mh2 : g_mh1;
    const __half* mc  = phase ? g_mc2 : g_mc1;
    const __half* Bt  = g_Bt16 + phase * 131072;

    const int r0 = tid >> 3;               // 0..31
    const int q  = tid & 7;
    const uint32_t sw0 = (uint32_t)(r0 * 128 + ((q ^ (r0 & 7)) << 4));
    const int gr0 = row0 + r0;
    const long grc0 = (long)gr0 * HDIM + q * 8;
    // B: smem row r = r0 + 32i -> g=(r0>>3)&3 (invariant), hh = i*8 + (r0&7)
    const __half* pB0 = Bt + (size_t)(((r0 >> 3) & 3) * 128 + h0 + (r0 & 7)) * 256 + q * 8;

    auto stage = [&](int j, int b) {
        const __half* Ap = (j < 2) ? Axx : Amh;
        const int koff = (j & 1) * 64;
        const int k0 = j * 64;
        const uint32_t abase = sbase + (b ? S_A1 : S_A0) + sw0;
        const uint32_t bbase = sbase + (b ? S_B1 : S_B0) + sw0;
#pragma unroll
        for (int i = 0; i < 4; ++i) {
            int ok = (gr0 + 32 * i < nrows) ? 16 : 0;
            cp_async16(abase + 4096u * i, Ap + grc0 + 4096 * i + koff, ok);
        }
#pragma unroll
        for (int i = 0; i < 4; ++i)
            cp_async16(bbase + 4096u * i, pB0 + 2048 * i + k0, 16);   // +8 weight cols per i
        cp_commit();
    };

    const int lane = tid & 31;
    const int warp = tid >> 5;
    const int wm = warp & 1;
    const int wn = warp >> 1;
    const int g8  = lane >> 2;
    const int tig = lane & 3;
    const int lane7 = lane & 7;

    const uint32_t a_row_off = (uint32_t)(wm * 64 + (lane & 15)) * 128;
    const int a_qsel = lane >> 4;
    const uint32_t b_row_off = (uint32_t)(wn * 32 + lane7 + ((lane >> 4) << 3)) * 128;
    const int b_qsel = (lane >> 3) & 1;

    float acc[4][4][4];
#pragma unroll
    for (int a = 0; a < 4; ++a)
#pragma unroll
        for (int b = 0; b < 4; ++b)
#pragma unroll
            for (int c = 0; c < 4; ++c) acc[a][b][c] = 0.f;

    stage(0, 0);

    for (int j = 0; j < 4; ++j) {
        const int buf = j & 1;
        if (j < 3) { stage(j + 1, buf ^ 1); cp_wait1(); }
        else       { cp_wait0(); }
        __syncthreads();

        const uint32_t Abase = sbase + (buf ? S_A1 : S_A0);
        const uint32_t Bbase = sbase + (buf ? S_B1 : S_B0);

#pragma unroll
        for (int ks = 0; ks < 4; ++ks) {
            uint32_t af[4][4], bf[4][2];
            const uint32_t axor = (uint32_t)(((2 * ks + a_qsel) ^ lane7) << 4);
            const uint32_t bxor = (uint32_t)(((2 * ks + b_qsel) ^ lane7) << 4);
#pragma unroll
            for (int mt = 0; mt < 4; ++mt)
                ldsm_x4(af[mt][0], af[mt][1], af[mt][2], af[mt][3],
                        Abase + a_row_off + (uint32_t)mt * 2048 + axor);
            ldsm_x4(bf[0][0], bf[0][1], bf[1][0], bf[1][1], Bbase + b_row_off + bxor);
            ldsm_x4(bf[2][0], bf[2][1], bf[3][0], bf[3][1], Bbase + b_row_off + 2048 + bxor);
#pragma unroll
            for (int mt = 0; mt < 4; ++mt)
#pragma unroll
                for (int nt = 0; nt < 4; ++nt)
                    mma_f16(acc[mt][nt], af[mt][0], af[mt][1], af[mt][2], af[mt][3],
                            bf[nt][0], bf[nt][1]);
        }
        if (j < 3) __syncthreads();
    }

    // ---- in-register gate epilogue ----
    // thread covers rows wm*64+mt*16+g8 (+8), cols hh = wn*8 + 2*tig + e (e=0,1)
    // acc[mt][g][j]: j = e for row, j = 2+e for row+8; g = gate (i,o,u,f)
    {
        const int hh0 = h0 + wn * 8 + tig * 2;
        float bias[4][2];
#pragma unroll
        for (int g = 0; g < 4; ++g) {
#pragma unroll
            for (int ee = 0; ee < 2; ++ee)
                bias[g][ee] = bW[g * 128 + hh0 + ee] + bU[g * 128 + hh0 + ee];
        }
#pragma unroll
        for (int mt = 0; mt < 4; ++mt) {
#pragma unroll
            for (int rh = 0; rh < 2; ++rh) {
                int grow = row0 + wm * 64 + mt * 16 + g8 + rh * 8;
                if (grow >= nrows) continue;
                const int j0 = rh * 2;
                float cn[2], hn[2];
                __half2 m2 = *(const __half2*)(mc + (size_t)grow * HDIM + hh0);
                float mcf[2] = { __low2float(m2), __high2float(m2) };
#pragma unroll
                for (int ee = 0; ee < 2; ++ee) {
                    float xi = acc[mt][0][j0 + ee] + bias[0][ee];
                    float xo = acc[mt][1][j0 + ee] + bias[1][ee];
                    float xu = acc[mt][2][j0 + ee] + bias[2][ee];
                    float xf = acc[mt][3][j0 + ee] + bias[3][ee];
                    float cnv = sigmoid_f(xi) * tanh_f(xu) + sigmoid_f(xf) * mcf[ee];
                    cn[ee] = cnv;
                    hn[ee] = sigmoid_f(xo) * tanh_f(cnv);
                }
                *(float2*)(c_out + (size_t)grow * HDIM + hh0) = make_float2(cn[0], cn[1]);
                *(float2*)(h_out + (size_t)grow * HDIM + hh0) = make_float2(hn[0], hn[1]);
                if (phase == 0)
                    *(__half2*)(g_c1n16 + (size_t)grow * HDIM + hh0) =
                        __floats2half2_rn(cn[0], cn[1]);
            }
        }
    }
}

// ---------------- host ----------------
extern "C" void kernel_launch(void* const* d_in, const int* in_sizes, int n_in,
                              void* d_out, int out_size)
{
    const float* x   = (const float*)d_in[0];
    const float* h1  = (const float*)d_in[1];
    const float* c1  = (const float*)d_in[2];
    const float* h2  = (const float*)d_in[3];
    const float* c2  = (const float*)d_in[4];
    const float* W1  = (const float*)d_in[5];
    const float* bW1 = (const float*)d_in[6];
    const float* U1  = (const float*)d_in[7];
    const float* bU1 = (const float*)d_in[8];
    const float* W2  = (const float*)d_in[9];
    const float* bW2 = (const float*)d_in[10];
    const float* U2  = (const float*)d_in[11];
    const float* bU2 = (const float*)d_in[12];
    const int*   src = (const int*)d_in[13];
    const int*   dst = (const int*)d_in[14];

    int n = in_sizes[1] / HDIM;
    int e = in_sizes[13];

    float* out = (float*)d_out;
    float* h1n = out;
    float* c1n = out + (size_t)n * HDIM;
    float* h2n = out + 2 * (size_t)n * HDIM;
    float* c2n = out + 3 * (size_t)n * HDIM;

    static int inited = 0;
    static cudaStream_t sG;
    static cudaEvent_t evFork, evG1[NCH], evG2[NCH];
    if (!inited) {
        cudaFuncSetAttribute(lstm_mma_kernel,
                             cudaFuncAttributeMaxDynamicSharedMemorySize, SMEM_TOTAL);
        int plo, phi;
        cudaDeviceGetStreamPriorityRange(&plo, &phi);
        cudaStreamCreateWithPriority(&sG, cudaStreamNonBlocking, phi);
        cudaEventCreateWithFlags(&evFork, cudaEventDisableTiming);
        for (int k = 0; k < NCH; ++k) {
            cudaEventCreateWithFlags(&evG1[k], cudaEventDisableTiming);
            cudaEventCreateWithFlags(&evG2[k], cudaEventDisableTiming);
        }
        inited = 1;
    }

    int mtiles = (n + 127) / 128;
    int mt_per = (mtiles + NCH - 1) / NCH;

    cudaEventRecord(evFork, 0);
    cudaStreamWaitEvent(sG, evFork, 0);

    seg_kernel<<<(e + 256) / 256, 256, 0, sG>>>(dst, n, e);
    for (int k = 0; k < NCH; ++k) {
        int tb = k * mt_per, te = min(mtiles, tb + mt_per);
        if (tb >= te) { cudaEventRecord(evG1[k], sG); continue; }
        int n0 = tb * 128, n1 = min(n, te * 128);
        int cnt = n1 - n0;
        gather_kernel<<<(cnt * 32 + 255) / 256, 256, 0, sG>>>(h1, c1, src, n0, n1, 0);
        cudaEventRecord(evG1[k], sG);
    }
    for (int k = 0; k < NCH; ++k) {
        int tb = k * mt_per, te = min(mtiles, tb + mt_per);
        if (tb >= te) { cudaEventRecord(evG2[k], sG); continue; }
        int n0 = tb * 128, n1 = min(n, te * 128);
        int cnt = n1 - n0;
        gather_kernel<<<(cnt * 32 + 255) / 256, 256, 0, sG>>>(h2, c2, src, n0, n1, 1);
        cudaEventRecord(evG2[k], sG);
    }

    {
        dim3 pgrid(512, 2);
        prep_kernel<<<pgrid, 256>>>(W1, U1, W2, U2);
        x16_kernel<<<(n * 32 + 255) / 256, 256>>>(x, n * 32);
    }
    for (int k = 0; k < NCH; ++k) {
        int tb = k * mt_per, te = min(mtiles, tb + mt_per);
        if (tb >= te) continue;
        cudaStreamWaitEvent(0, evG1[k], 0);
        dim3 grid(4, te - tb);
        lstm_mma_kernel<<<grid, 256, SMEM_TOTAL>>>(bW1, bU1, h1n, c1n, n, 0, tb);
    }
    for (int k = 0; k < NCH; ++k) {
        int tb = k * mt_per, te = min(mtiles, tb + mt_per);
        if (tb >= te) continue;
        cudaStreamWaitEvent(0, evG2[k], 0);
        dim3 grid(4, te - tb);
        lstm_mma_kernel<<<grid, 256, SMEM_TOTAL>>>(bW2, bU2, h2n, c2n, n, 1, tb);
    }
}

// round 17
// speedup vs baseline: 2.0526x; 1.0023x over previous
#include <cuda_runtime.h>
#include <cuda_fp16.h>
#include <cstdint>
#include <math.h>

#define HDIM 128
#define MAXN 200000
#define NCH 4

// ---------------- device scratch ----------------
__device__ __half g_x16[MAXN * HDIM];     // fp16 x
__device__ __half g_c1n16[MAXN * HDIM];   // fp16 c1n (phase-0 output)
__device__ __half g_h116[MAXN * HDIM];    // fp16 copies of gather inputs
__device__ __half g_c116[MAXN * HDIM];
__device__ __half g_h216[MAXN * HDIM];
__device__ __half g_c216[MAXN * HDIM];
__device__ __half g_mh1[MAXN * HDIM];     // mailbox h sums, fp16
__device__ __half g_mh2[MAXN * HDIM];
__device__ __half g_mc1[MAXN * HDIM];     // mailbox c sums, fp16
__device__ __half g_mc2[MAXN * HDIM];
__device__ int    g_seg[MAXN + 1];
__device__ __half g_Bt16[2 * 512 * 256];  // [phase][n=512][k=256]

__device__ __forceinline__ uint32_t smem_u32(const void* p) {
    uint32_t a;
    asm("{ .reg .u64 t; cvta.to.shared.u64 t, %1; cvt.u32.u64 %0, t; }" : "=r"(a) : "l"(p));
    return a;
}
__device__ __forceinline__ void cp_async16(uint32_t dst, const void* src, int src_bytes) {
    asm volatile("cp.async.cg.shared.global [%0], [%1], 16, %2;"
                 :: "r"(dst), "l"(src), "r"(src_bytes) : "memory");
}
__device__ __forceinline__ void cp_commit() {
    asm volatile("cp.async.commit_group;" ::: "memory");
}
__device__ __forceinline__ void cp_wait1() {
    asm volatile("cp.async.wait_group 1;" ::: "memory");
}
__device__ __forceinline__ void cp_wait0() {
    asm volatile("cp.async.wait_group 0;" ::: "memory");
}
__device__ __forceinline__ void mma_f16(float* d, uint32_t a0, uint32_t a1, uint32_t a2,
                                        uint32_t a3, uint32_t b0, uint32_t b1) {
    asm volatile(
        "mma.sync.aligned.m16n8k16.row.col.f32.f16.f16.f32 "
        "{%0,%1,%2,%3}, {%4,%5,%6,%7}, {%8,%9}, {%0,%1,%2,%3};"
        : "+f"(d[0]), "+f"(d[1]), "+f"(d[2]), "+f"(d[3])
        : "r"(a0), "r"(a1), "r"(a2), "r"(a3), "r"(b0), "r"(b1));
}
__device__ __forceinline__ void ldsm_x4(uint32_t& r0, uint32_t& r1, uint32_t& r2, uint32_t& r3,
                                        uint32_t addr) {
    asm volatile("ldmatrix.sync.aligned.m8n8.x4.shared.b16 {%0,%1,%2,%3}, [%4];"
                 : "=r"(r0), "=r"(r1), "=r"(r2), "=r"(r3) : "r"(addr));
}
__device__ __forceinline__ float sigmoid_f(float x) {
    return __fdividef(1.f, 1.f + __expf(-x));
}
__device__ __forceinline__ float tanh_f(float x) {
    return 1.f - __fdividef(2.f, __expf(2.f * x) + 1.f);
}
__device__ __forceinline__ void h2pair(uint32_t u, float& a, float& b) {
    __half2 h = *(__half2*)&u;
    a = __low2float(h); b = __high2float(h);
}

// ---------------- seg ----------------
__global__ void seg_kernel(const int* __restrict__ dst, int n, int e)
{
    int i = blockIdx.x * blockDim.x + threadIdx.x;
    if (i > e) return;
    int lo = (i == 0) ? 0 : dst[i - 1] + 1;
    int hi = (i == e) ? n : dst[i];
    for (int v = lo; v <= hi; ++v) g_seg[v] = i;
}

// ---------------- float -> half into device-global selected in-kernel ----------------
__global__ void f2h_kernel(const float* __restrict__ a, int which, int total4)
{
    int i = blockIdx.x * blockDim.x + threadIdx.x;
    if (i >= total4) return;
    __half* o = (which == 0) ? g_h116 : (which == 1) ? g_c116 :
                (which == 2) ? g_h216 : (which == 3) ? g_c216 : g_x16;
    float4 v = *(const float4*)(a + i * 4);
    __half2 lo = __floats2half2_rn(v.x, v.y);
    __half2 hi = __floats2half2_rn(v.z, v.w);
    uint2 o2; o2.x = *(uint32_t*)&lo; o2.y = *(uint32_t*)&hi;
    *(uint2*)(o + i * 4) = o2;
}

// ---------------- gather over fp16 device-global inputs ----------------
__global__ void gather_kernel(const int* __restrict__ src, int n0, int n1, int level)
{
    int node = ((blockIdx.x * blockDim.x + threadIdx.x) >> 5) + n0;
    int lane = threadIdx.x & 31;
    if (node >= n1) return;

    const __half* ha = level ? g_h216 : g_h116;
    const __half* ca = level ? g_c216 : g_c116;
    __half* mh = level ? g_mh2 : g_mh1;
    __half* mc = level ? g_mc2 : g_mc1;

    int s    = g_seg[node];
    int send = g_seg[node + 1];

    float4 ah = make_float4(0.f, 0.f, 0.f, 0.f);
    float4 ac = ah;
    const int col = lane * 4;

    int idx = s;
    for (; idx + 4 <= send; idx += 4) {
        int b0 = src[idx + 0] * HDIM + col;
        int b1 = src[idx + 1] * HDIM + col;
        int b2 = src[idx + 2] * HDIM + col;
        int b3 = src[idx + 3] * HDIM + col;
        uint2 vh0 = *(const uint2*)(ha + b0), vh1 = *(const uint2*)(ha + b1);
        uint2 vh2 = *(const uint2*)(ha + b2), vh3 = *(const uint2*)(ha + b3);
        uint2 vc0 = *(const uint2*)(ca + b0), vc1 = *(const uint2*)(ca + b1);
        uint2 vc2 = *(const uint2*)(ca + b2), vc3 = *(const uint2*)(ca + b3);
        float p, qf;
        h2pair(vh0.x, p, qf); ah.x += p; ah.y += qf;
        h2pair(vh0.y, p, qf); ah.z += p; ah.w += qf;
        h2pair(vh1.x, p, qf); ah.x += p; ah.y += qf;
        h2pair(vh1.y, p, qf); ah.z += p; ah.w += qf;
        h2pair(vh2.x, p, qf); ah.x += p; ah.y += qf;
        h2pair(vh2.y, p, qf); ah.z += p; ah.w += qf;
        h2pair(vh3.x, p, qf); ah.x += p; ah.y += qf;
        h2pair(vh3.y, p, qf); ah.z += p; ah.w += qf;
        h2pair(vc0.x, p, qf); ac.x += p; ac.y += qf;
        h2pair(vc0.y, p, qf); ac.z += p; ac.w += qf;
        h2pair(vc1.x, p, qf); ac.x += p; ac.y += qf;
        h2pair(vc1.y, p, qf); ac.z += p; ac.w += qf;
        h2pair(vc2.x, p, qf); ac.x += p; ac.y += qf;
        h2pair(vc2.y, p, qf); ac.z += p; ac.w += qf;
        h2pair(vc3.x, p, qf); ac.x += p; ac.y += qf;
        h2pair(vc3.y, p, qf); ac.z += p; ac.w += qf;
    }
    for (; idx < send; ++idx) {
        int b = src[idx] * HDIM + col;
        uint2 vh = *(const uint2*)(ha + b);
        uint2 vc = *(const uint2*)(ca + b);
        float p, qf;
        h2pair(vh.x, p, qf); ah.x += p; ah.y += qf;
        h2pair(vh.y, p, qf); ah.z += p; ah.w += qf;
        h2pair(vc.x, p, qf); ac.x += p; ac.y += qf;
        h2pair(vc.y, p, qf); ac.z += p; ac.w += qf;
    }

    int ob = node * HDIM + col;
    {
        __half2 lo = __floats2half2_rn(ah.x, ah.y);
        __half2 hi = __floats2half2_rn(ah.z, ah.w);
        uint2 o; o.x = *(uint32_t*)&lo; o.y = *(uint32_t*)&hi;
        *(uint2*)(mh + ob) = o;
    }
    {
        __half2 lo = __floats2half2_rn(ac.x, ac.y);
        __half2 hi = __floats2half2_rn(ac.z, ac.w);
        uint2 o; o.x = *(uint32_t*)&lo; o.y = *(uint32_t*)&hi;
        *(uint2*)(mc + ob) = o;
    }
}

// ---------------- prep ----------------
__global__ void prep_kernel(const float* __restrict__ W1, const float* __restrict__ U1,
                            const float* __restrict__ W2, const float* __restrict__ U2)
{
    int p = blockIdx.y;
    int i = blockIdx.x * 256 + threadIdx.x;
    int k = i >> 9, n = i & 511;
    const float* W = p ? W2 : W1;
    const float* U = p ? U2 : U1;
    float v = (k < 128) ? W[k * 512 + n] : U[(k - 128) * 512 + n];
    g_Bt16[p * 131072 + n * 256 + k] = __float2half_rn(v);
}

// ---------------- fused HMMA(fp16) GEMM + in-register gates ----------------
#define S_A0 0
#define S_B0 16384
#define S_A1 32768
#define S_B1 49152
#define SMEM_TOTAL 65536

__global__ __launch_bounds__(256, 2)
void lstm_mma_kernel(const float* __restrict__ bW, const float* __restrict__ bU,
                     float* __restrict__ h_out, float* __restrict__ c_out,
                     int nrows, int phase, int tile_base)
{
    extern __shared__ char smem[];
    const uint32_t sbase = smem_u32(smem);
    const int tid = threadIdx.x;
    const int h0   = blockIdx.x * 32;
    const int row0 = (blockIdx.y + tile_base) * 128;

    const __half* Axx = phase ? g_c1n16 : g_x16;
    const __half* Amh = phase ? g_mh2 : g_mh1;
    const __half* mc  = phase ? g_mc2 : g_mc1;
    const __half* Bt  = g_Bt16 + phase * 131072;

    const int r0 = tid >> 3;
    const int q  = tid & 7;
    const uint32_t sw0 = (uint32_t)(r0 * 128 + ((q ^ (r0 & 7)) << 4));
    const int gr0 = row0 + r0;
    const long grc0 = (long)gr0 * HDIM + q * 8;
    const __half* pB0 = Bt + (size_t)(((r0 >> 3) & 3) * 128 + h0 + (r0 & 7)) * 256 + q * 8;

    auto stage = [&](int j, int b) {
        const __half* Ap = (j < 2) ? Axx : Amh;
        const int koff = (j & 1) * 64;
        const int k0 = j * 64;
        const uint32_t abase = sbase + (b ? S_A1 : S_A0) + sw0;
        const uint32_t bbase = sbase + (b ? S_B1 : S_B0) + sw0;
#pragma unroll
        for (int i = 0; i < 4; ++i) {
            int ok = (gr0 + 32 * i < nrows) ? 16 : 0;
            cp_async16(abase + 4096u * i, Ap + grc0 + 4096 * i + koff, ok);
        }
#pragma unroll
        for (int i = 0; i < 4; ++i)
            cp_async16(bbase + 4096u * i, pB0 + 2048 * i + k0, 16);
        cp_commit();
    };

    const int lane = tid & 31;
    const int warp = tid >> 5;
    const int wm = warp & 1;
    const int wn = warp >> 1;
    const int g8  = lane >> 2;
    const int tig = lane & 3;
    const int lane7 = lane & 7;

    const uint32_t a_row_off = (uint32_t)(wm * 64 + (lane & 15)) * 128;
    const int a_qsel = lane >> 4;
    const uint32_t b_row_off = (uint32_t)(wn * 32 + lane7 + ((lane >> 4) << 3)) * 128;
    const int b_qsel = (lane >> 3) & 1;

    float acc[4][4][4];
#pragma unroll
    for (int a = 0; a < 4; ++a)
#pragma unroll
        for (int b = 0; b < 4; ++b)
#pragma unroll
            for (int c = 0; c < 4; ++c) acc[a][b][c] = 0.f;

    stage(0, 0);

    for (int j = 0; j < 4; ++j) {
        const int buf = j & 1;
        if (j < 3) { stage(j + 1, buf ^ 1); cp_wait1(); }
        else       { cp_wait0(); }
        __syncthreads();

        const uint32_t Abase = sbase + (buf ? S_A1 : S_A0);
        const uint32_t Bbase = sbase + (buf ? S_B1 : S_B0);

#pragma unroll
        for (int ks = 0; ks < 4; ++ks) {
            uint32_t af[4][4], bf[4][2];
            const uint32_t axor = (uint32_t)(((2 * ks + a_qsel) ^ lane7) << 4);
            const uint32_t bxor = (uint32_t)(((2 * ks + b_qsel) ^ lane7) << 4);
#pragma unroll
            for (int mt = 0; mt < 4; ++mt)
                ldsm_x4(af[mt][0], af[mt][1], af[mt][2], af[mt][3],
                        Abase + a_row_off + (uint32_t)mt * 2048 + axor);
            ldsm_x4(bf[0][0], bf[0][1], bf[1][0], bf[1][1], Bbase + b_row_off + bxor);
            ldsm_x4(bf[2][0], bf[2][1], bf[3][0], bf[3][1], Bbase + b_row_off + 2048 + bxor);
#pragma unroll
            for (int mt = 0; mt < 4; ++mt)
#pragma unroll
                for (int nt = 0; nt < 4; ++nt)
                    mma_f16(acc[mt][nt], af[mt][0], af[mt][1], af[mt][2], af[mt][3],
                            bf[nt][0], bf[nt][1]);
        }
        if (j < 3) __syncthreads();
    }

    // ---- in-register gate epilogue ----
    {
        const int hh0 = h0 + wn * 8 + tig * 2;
        float bias[4][2];
#pragma unroll
        for (int g = 0; g < 4; ++g) {
#pragma unroll
            for (int ee = 0; ee < 2; ++ee)
                bias[g][ee] = bW[g * 128 + hh0 + ee] + bU[g * 128 + hh0 + ee];
        }
#pragma unroll
        for (int mt = 0; mt < 4; ++mt) {
#pragma unroll
            for (int rh = 0; rh < 2; ++rh) {
                int grow = row0 + wm * 64 + mt * 16 + g8 + rh * 8;
                if (grow >= nrows) continue;
                const int j0 = rh * 2;
                float cn[2], hn[2];
                __half2 m2 = *(const __half2*)(mc + (size_t)grow * HDIM + hh0);
                float mcf[2] = { __low2float(m2), __high2float(m2) };
#pragma unroll
                for (int ee = 0; ee < 2; ++ee) {
                    float xi = acc[mt][0][j0 + ee] + bias[0][ee];
                    float xo = acc[mt][1][j0 + ee] + bias[1][ee];
                    float xu = acc[mt][2][j0 + ee] + bias[2][ee];
                    float xf = acc[mt][3][j0 + ee] + bias[3][ee];
                    float cnv = sigmoid_f(xi) * tanh_f(xu) + sigmoid_f(xf) * mcf[ee];
                    cn[ee] = cnv;
                    hn[ee] = sigmoid_f(xo) * tanh_f(cnv);
                }
                *(float2*)(c_out + (size_t)grow * HDIM + hh0) = make_float2(cn[0], cn[1]);
                *(float2*)(h_out + (size_t)grow * HDIM + hh0) = make_float2(hn[0], hn[1]);
                if (phase == 0)
                    *(__half2*)(g_c1n16 + (size_t)grow * HDIM + hh0) =
                        __floats2half2_rn(cn[0], cn[1]);
            }
        }
    }
}

// ---------------- host ----------------
extern "C" void kernel_launch(void* const* d_in, const int* in_sizes, int n_in,
                              void* d_out, int out_size)
{
    const float* x   = (const float*)d_in[0];
    const float* h1  = (const float*)d_in[1];
    const float* c1  = (const float*)d_in[2];
    const float* h2  = (const float*)d_in[3];
    const float* c2  = (const float*)d_in[4];
    const float* W1  = (const float*)d_in[5];
    const float* bW1 = (const float*)d_in[6];
    const float* U1  = (const float*)d_in[7];
    const float* bU1 = (const float*)d_in[8];
    const float* W2  = (const float*)d_in[9];
    const float* bW2 = (const float*)d_in[10];
    const float* U2  = (const float*)d_in[11];
    const float* bU2 = (const float*)d_in[12];
    const int*   src = (const int*)d_in[13];
    const int*   dst = (const int*)d_in[14];

    int n = in_sizes[1] / HDIM;
    int e = in_sizes[13];

    float* out = (float*)d_out;
    float* h1n = out;
    float* c1n = out + (size_t)n * HDIM;
    float* h2n = out + 2 * (size_t)n * HDIM;
    float* c2n = out + 3 * (size_t)n * HDIM;

    static int inited = 0;
    static cudaStream_t sG;
    static cudaEvent_t evFork, evCA, evCB, evG1[NCH], evG2[NCH];
    if (!inited) {
        cudaFuncSetAttribute(lstm_mma_kernel,
                             cudaFuncAttributeMaxDynamicSharedMemorySize, SMEM_TOTAL);
        int plo, phi;
        cudaDeviceGetStreamPriorityRange(&plo, &phi);
        cudaStreamCreateWithPriority(&sG, cudaStreamNonBlocking, phi);
        cudaEventCreateWithFlags(&evFork, cudaEventDisableTiming);
        cudaEventCreateWithFlags(&evCA, cudaEventDisableTiming);
        cudaEventCreateWithFlags(&evCB, cudaEventDisableTiming);
        for (int k = 0; k < NCH; ++k) {
            cudaEventCreateWithFlags(&evG1[k], cudaEventDisableTiming);
            cudaEventCreateWithFlags(&evG2[k], cudaEventDisableTiming);
        }
        inited = 1;
    }

    int mtiles = (n + 127) / 128;
    int mt_per = (mtiles + NCH - 1) / NCH;
    int t4 = n * 32;                 // n*128/4
    int cblk = (t4 + 255) / 256;

    cudaEventRecord(evFork, 0);
    cudaStreamWaitEvent(sG, evFork, 0);

    // main: conversions first (producers for gathers + GEMM A operands)
    f2h_kernel<<<cblk, 256>>>(h1, 0, t4);
    f2h_kernel<<<cblk, 256>>>(c1, 1, t4);
    cudaEventRecord(evCA, 0);
    f2h_kernel<<<cblk, 256>>>(h2, 2, t4);
    f2h_kernel<<<cblk, 256>>>(c2, 3, t4);
    cudaEventRecord(evCB, 0);
    {
        dim3 pgrid(512, 2);
        prep_kernel<<<pgrid, 256>>>(W1, U1, W2, U2);
        f2h_kernel<<<cblk, 256>>>(x, 4, t4);
    }

    // sG: seg, then gather1 chunks (after convA), then gather2 chunks (after convB)
    seg_kernel<<<(e + 256) / 256, 256, 0, sG>>>(dst, n, e);
    cudaStreamWaitEvent(sG, evCA, 0);
    for (int k = 0; k < NCH; ++k) {
        int tb = k * mt_per, te = min(mtiles, tb + mt_per);
        if (tb >= te) { cudaEventRecord(evG1[k], sG); continue; }
        int n0 = tb * 128, n1 = min(n, te * 128);
        int cnt = n1 - n0;
        gather_kernel<<<(cnt * 32 + 255) / 256, 256, 0, sG>>>(src, n0, n1, 0);
        cudaEventRecord(evG1[k], sG);
    }
    cudaStreamWaitEvent(sG, evCB, 0);
    for (int k = 0; k < NCH; ++k) {
        int tb = k * mt_per, te = min(mtiles, tb + mt_per);
        if (tb >= te) { cudaEventRecord(evG2[k], sG); continue; }
        int n0 = tb * 128, n1 = min(n, te * 128);
        int cnt = n1 - n0;
        gather_kernel<<<(cnt * 32 + 255) / 256, 256, 0, sG>>>(src, n0, n1, 1);
        cudaEventRecord(evG2[k], sG);
    }

    // main: chunked GEMMs
    for (int k = 0; k < NCH; ++k) {
        int tb = k * mt_per, te = min(mtiles, tb + mt_per);
        if (tb >= te) continue;
        cudaStreamWaitEvent(0, evG1[k], 0);
        dim3 grid(4, te - tb);
        lstm_mma_kernel<<<grid, 256, SMEM_TOTAL>>>(bW1, bU1, h1n, c1n, n, 0, tb);
    }
    for (int k = 0; k < NCH; ++k) {
        int tb = k * mt_per, te = min(mtiles, tb + mt_per);
        if (tb >= te) continue;
        cudaStreamWaitEvent(0, evG2[k], 0);
        dim3 grid(4, te - tb);
        lstm_mma_kernel<<<grid, 256, SMEM_TOTAL>>>(bW2, bU2, h2n, c2n, n, 1, tb);
    }
}